// round 4
// baseline (speedup 1.0000x reference)
#include <cuda_runtime.h>
#include <cuda_bf16.h>
#include <cstdint>

// Problem dims (fixed)
#define BSZ      2
#define LEN      2048
#define DMODEL   1024
#define DSTATE   16
#define DCONV    4
#define DINNER   2048
#define MROWS    (BSZ * LEN)          // 4096
#define N_XZ     (2 * DINNER)         // 4096

// ---------------- scratch (device globals; no allocs allowed) ----------------
__device__ float g_xz[(size_t)MROWS * N_XZ];       // [4096, 4096]  x_proj | z
__device__ float g_xact[(size_t)MROWS * DINNER];   // [4096, 2048]
__device__ float g_dt[(size_t)MROWS * DINNER];     // [4096, 2048]
__device__ float g_yg[(size_t)MROWS * DINNER];     // [4096, 2048]

// ---------------- fast math helpers (FMA-pipe exp2, avoid MUFU storms) -------
__device__ __forceinline__ float fexp2(float x) {
    // 2^x, |err| ~ 1e-7 rel on [-0.5,0.5] fraction; valid for x in [-125,125]
    x = fminf(fmaxf(x, -125.0f), 125.0f);
    float r = rintf(x);
    float f = x - r;
    float p = 1.5403530e-4f;
    p = fmaf(p, f, 1.3333558e-3f);
    p = fmaf(p, f, 9.6181291e-3f);
    p = fmaf(p, f, 5.5504109e-2f);
    p = fmaf(p, f, 2.4022651e-1f);
    p = fmaf(p, f, 6.9314718e-1f);
    p = fmaf(p, f, 1.0f);
    int ir = (int)r;
    float sc = __int_as_float((ir + 127) << 23);
    return p * sc;
}
#define LOG2E 1.44269504f

__device__ __forceinline__ float fast_sigmoid(float x) {
    float e = fexp2(-x * LOG2E);
    return __fdividef(1.0f, 1.0f + e);
}
__device__ __forceinline__ float fast_softplus(float v) {
    float e = fexp2(-fabsf(v) * LOG2E);
    return fmaxf(v, 0.0f) + __logf(1.0f + e);
}

// ---------------- tiled fp32 SGEMM: C[M,N] = A[M,K] * B[N,K]^T ---------------
// epi: 0 = plain store, 1 = softplus(acc + bias[n])
#define BM 128
#define BN 128
#define BKK 16
__global__ void __launch_bounds__(256)
sgemm_tn(const float* __restrict__ A, const float* __restrict__ Bm,
         float* __restrict__ C, int M, int N, int K,
         const float* __restrict__ bias, int epi)
{
    __shared__ float As[BKK][BM];
    __shared__ float Bs[BKK][BN];
    const int tid = threadIdx.x;
    const int bx = blockIdx.x;   // N tile
    const int by = blockIdx.y;   // M tile

    const float* Ab = A + (size_t)by * BM * K;
    const float* Bb = Bm + (size_t)bx * BN * K;

    const int lrow = tid >> 2;          // 0..63
    const int lcol = (tid & 3) << 2;    // 0,4,8,12

    const int tx = tid & 15;
    const int ty = tid >> 4;

    float acc[8][8];
#pragma unroll
    for (int i = 0; i < 8; ++i)
#pragma unroll
        for (int j = 0; j < 8; ++j) acc[i][j] = 0.0f;

    for (int k0 = 0; k0 < K; k0 += BKK) {
#pragma unroll
        for (int r = 0; r < 2; ++r) {
            int row = lrow + r * 64;
            float4 va = *(const float4*)(Ab + (size_t)row * K + k0 + lcol);
            As[lcol + 0][row] = va.x;
            As[lcol + 1][row] = va.y;
            As[lcol + 2][row] = va.z;
            As[lcol + 3][row] = va.w;
            float4 vb = *(const float4*)(Bb + (size_t)row * K + k0 + lcol);
            Bs[lcol + 0][row] = vb.x;
            Bs[lcol + 1][row] = vb.y;
            Bs[lcol + 2][row] = vb.z;
            Bs[lcol + 3][row] = vb.w;
        }
        __syncthreads();
#pragma unroll
        for (int kk = 0; kk < BKK; ++kk) {
            float ra[8], rb[8];
            *(float4*)&ra[0] = *(const float4*)&As[kk][ty * 8];
            *(float4*)&ra[4] = *(const float4*)&As[kk][ty * 8 + 4];
            *(float4*)&rb[0] = *(const float4*)&Bs[kk][tx * 8];
            *(float4*)&rb[4] = *(const float4*)&Bs[kk][tx * 8 + 4];
#pragma unroll
            for (int i = 0; i < 8; ++i)
#pragma unroll
                for (int j = 0; j < 8; ++j)
                    acc[i][j] = fmaf(ra[i], rb[j], acc[i][j]);
        }
        __syncthreads();
    }

#pragma unroll
    for (int i = 0; i < 8; ++i) {
        int gr = by * BM + ty * 8 + i;
#pragma unroll
        for (int j = 0; j < 8; ++j) {
            int gc = bx * BN + tx * 8 + j;
            float v = acc[i][j];
            if (epi == 1) v = fast_softplus(v + bias[gc]);
            C[(size_t)gr * N + gc] = v;
        }
    }
}

// ---------------- depthwise causal conv1d (k=4) + SiLU -----------------------
__global__ void __launch_bounds__(256)
conv_silu_kernel(const float* __restrict__ conv_w, const float* __restrict__ conv_b)
{
    int idx = blockIdx.x * blockDim.x + threadIdx.x;   // over MROWS*DINNER
    int d = idx & (DINNER - 1);
    int row = idx >> 11;            // b*L + t
    int t = row & (LEN - 1);

    float acc = conv_b[d];
    const float* w = conv_w + d * DCONV;
#pragma unroll
    for (int j = 0; j < DCONV; ++j) {
        int tt = t - (DCONV - 1) + j;
        if (tt >= 0)
            acc = fmaf(g_xz[(size_t)(row - (DCONV - 1) + j) * N_XZ + d], w[j], acc);
    }
    g_xact[idx] = acc * fast_sigmoid(acc);
}

// ---------------- selective scan + gating ------------------------------------
// one lane per (b, d, s); 16 lanes per channel; 2 channels per warp.
__global__ void __launch_bounds__(256)
scan_kernel(const float* __restrict__ A_log, const float* __restrict__ Dp)
{
    const int lane16 = threadIdx.x & 15;           // state index s
    const int grp = threadIdx.x >> 4;              // channel group in block (0..15)
    const int c = blockIdx.x * 16 + grp;           // 0..4095
    const int b = c >> 11;
    const int d = c & (DINNER - 1);

    // a = -exp(A_log) * log2(e), so exp(dt*A) = 2^(dt*a)
    const float a = -__expf(A_log[d * DSTATE + lane16]) * LOG2E;
    const float dp = Dp[d];

    const size_t base = (size_t)(b * LEN) * DINNER + d;
    const size_t zbase = (size_t)(b * LEN) * N_XZ + DINNER + d;

    float h = 0.0f;
    float dt = g_dt[base];
    float xv = g_xact[base];

    for (int t = 0; t < LEN; ++t) {
        int tn = (t + 1 < LEN) ? (t + 1) : t;
        float dt_n = g_dt[base + (size_t)tn * DINNER];
        float xv_n = g_xact[base + (size_t)tn * DINNER];

        float dA = fexp2(dt * a);
        h = fmaf(dA, h, dt * xv);

        float s = h;
        s += __shfl_xor_sync(0xffffffffu, s, 1);
        s += __shfl_xor_sync(0xffffffffu, s, 2);
        s += __shfl_xor_sync(0xffffffffu, s, 4);
        s += __shfl_xor_sync(0xffffffffu, s, 8);

        if (lane16 == 0) {
            float y = s + dp * xv;
            float z = g_xz[zbase + (size_t)t * N_XZ];
            g_yg[base + (size_t)t * DINNER] = y * (z * fast_sigmoid(z));
        }
        dt = dt_n;
        xv = xv_n;
    }
}

// ---------------- launch ------------------------------------------------------
extern "C" void kernel_launch(void* const* d_in, const int* in_sizes, int n_in,
                              void* d_out, int out_size)
{
    const float* x      = (const float*)d_in[0];   // [2,2048,1024]
    const float* W_in   = (const float*)d_in[1];   // [4096,1024]
    const float* conv_w = (const float*)d_in[2];   // [2048,1,4]
    const float* conv_b = (const float*)d_in[3];   // [2048]
    const float* A_log  = (const float*)d_in[4];   // [2048,16]
    const float* Dp     = (const float*)d_in[5];   // [2048]
    const float* W_dt   = (const float*)d_in[6];   // [2048,2048]
    const float* b_dt   = (const float*)d_in[7];   // [2048]
    const float* W_out  = (const float*)d_in[8];   // [1024,2048]
    float* out = (float*)d_out;                    // [2,2048,1024]

    float* xz = nullptr;  cudaGetSymbolAddress((void**)&xz, g_xz);
    float* xa = nullptr;  cudaGetSymbolAddress((void**)&xa, g_xact);
    float* dt = nullptr;  cudaGetSymbolAddress((void**)&dt, g_dt);
    float* yg = nullptr;  cudaGetSymbolAddress((void**)&yg, g_yg);

    // 1) xz = x @ W_in^T          [4096,1024] x [4096,1024]^T -> [4096,4096]
    {
        dim3 grid(N_XZ / BN, MROWS / BM);
        sgemm_tn<<<grid, 256>>>(x, W_in, xz, MROWS, N_XZ, DMODEL, nullptr, 0);
    }
    // 2) depthwise conv + SiLU -> g_xact
    {
        int total = MROWS * DINNER;
        conv_silu_kernel<<<total / 256, 256>>>(conv_w, conv_b);
    }
    // 3) dt = softplus(x_act @ W_dt^T + b_dt)   -> g_dt
    {
        dim3 grid(DINNER / BN, MROWS / BM);
        sgemm_tn<<<grid, 256>>>(xa, W_dt, dt, MROWS, DINNER, DINNER, b_dt, 1);
    }
    // 4) selective scan + gate -> g_yg
    {
        scan_kernel<<<(BSZ * DINNER) / 16, 256>>>(A_log, Dp);
    }
    // 5) out = y_gated @ W_out^T  [4096,2048] x [1024,2048]^T -> [4096,1024]
    {
        dim3 grid(DMODEL / BN, MROWS / BM);
        sgemm_tn<<<grid, 256>>>(yg, W_out, out, MROWS, DMODEL, DINNER, nullptr, 0);
    }
}

// round 10
// speedup vs baseline: 2.3931x; 2.3931x over previous
#include <cuda_runtime.h>
#include <cuda_bf16.h>
#include <cstdint>

// Problem dims (fixed)
#define BSZ      2
#define LEN      2048
#define DMODEL   1024
#define DSTATE   16
#define DCONV    4
#define DINNER   2048
#define MROWS    (BSZ * LEN)          // 4096
#define N_XZ     (2 * DINNER)         // 4096

// ---------------- scratch (device globals; no allocs allowed) ----------------
__device__ float g_xz[(size_t)MROWS * N_XZ];       // [4096, 4096]  x_proj | z
__device__ float g_xact[(size_t)MROWS * DINNER];   // [4096, 2048]
__device__ float g_dt[(size_t)MROWS * DINNER];     // [4096, 2048]
__device__ float g_yg[(size_t)MROWS * DINNER];     // [4096, 2048]

// bf16 hi/lo split buffers for tensor-core GEMMs
__device__ __nv_bfloat16 g_xh[(size_t)MROWS * DMODEL],  g_xl[(size_t)MROWS * DMODEL];
__device__ __nv_bfloat16 g_wih[(size_t)N_XZ * DMODEL],  g_wil[(size_t)N_XZ * DMODEL];
__device__ __nv_bfloat16 g_xah[(size_t)MROWS * DINNER], g_xal[(size_t)MROWS * DINNER];
__device__ __nv_bfloat16 g_wdh[(size_t)DINNER * DINNER],g_wdl[(size_t)DINNER * DINNER];
__device__ __nv_bfloat16 g_ygh[(size_t)MROWS * DINNER], g_ygl[(size_t)MROWS * DINNER];
__device__ __nv_bfloat16 g_woh[(size_t)DMODEL * DINNER],g_wol[(size_t)DMODEL * DINNER];

// ---------------- fast math helpers (FMA-pipe exp2, avoid MUFU storms) -------
__device__ __forceinline__ float fexp2(float x) {
    x = fminf(fmaxf(x, -125.0f), 125.0f);
    float r = rintf(x);
    float f = x - r;
    float p = 1.5403530e-4f;
    p = fmaf(p, f, 1.3333558e-3f);
    p = fmaf(p, f, 9.6181291e-3f);
    p = fmaf(p, f, 5.5504109e-2f);
    p = fmaf(p, f, 2.4022651e-1f);
    p = fmaf(p, f, 6.9314718e-1f);
    p = fmaf(p, f, 1.0f);
    int ir = (int)r;
    float sc = __int_as_float((ir + 127) << 23);
    return p * sc;
}
#define LOG2E 1.44269504f

__device__ __forceinline__ float fast_sigmoid(float x) {
    float e = fexp2(-x * LOG2E);
    return __fdividef(1.0f, 1.0f + e);
}
__device__ __forceinline__ float fast_softplus(float v) {
    float e = fexp2(-fabsf(v) * LOG2E);
    return fmaxf(v, 0.0f) + __logf(1.0f + e);
}

// ---------------- generic-PTX tensor helpers (sm_80+, compiles on compute_103)
__device__ __forceinline__ uint32_t smem_u32(const void* p) {
    uint32_t a;
    asm("{ .reg .u64 t; cvta.to.shared.u64 t, %1; cvt.u32.u64 %0, t; }" : "=r"(a) : "l"(p));
    return a;
}
__device__ __forceinline__ void cpasync16(uint32_t dst, const void* src) {
    asm volatile("cp.async.cg.shared.global [%0], [%1], 16;" :: "r"(dst), "l"(src));
}
__device__ __forceinline__ void cp_commit() {
    asm volatile("cp.async.commit_group;" ::: "memory");
}
__device__ __forceinline__ void ldsm4(uint32_t* r, uint32_t addr) {
    asm volatile("ldmatrix.sync.aligned.m8n8.x4.shared.b16 {%0,%1,%2,%3}, [%4];"
                 : "=r"(r[0]), "=r"(r[1]), "=r"(r[2]), "=r"(r[3]) : "r"(addr));
}
__device__ __forceinline__ void mma16816(float* c, const uint32_t* a, const uint32_t* b) {
    asm volatile(
        "mma.sync.aligned.m16n8k16.row.col.f32.bf16.bf16.f32 "
        "{%0,%1,%2,%3}, {%4,%5,%6,%7}, {%8,%9}, {%0,%1,%2,%3};"
        : "+f"(c[0]), "+f"(c[1]), "+f"(c[2]), "+f"(c[3])
        : "r"(a[0]), "r"(a[1]), "r"(a[2]), "r"(a[3]), "r"(b[0]), "r"(b[1]));
}

// ---------------- bf16-split HMMA GEMM ---------------------------------------
// C[M,N] = A[M,K] @ B[N,K]^T with A = Ah+Al, B = Bh+Bl (bf16 pairs), fp32 acc.
// CTA tile 128x128, K chunk 64, 8 warps (4m x 2n), warp tile 32x64.
// epi: 0 = plain store, 1 = softplus(acc + bias[n]).
#define RS     72                      // smem row stride in bf16 (padded, 144B)
#define TILEB  (128 * RS * 2)          // 18432 B per tile
#define BUFB   (4 * TILEB)             // Ah, Al, Bh, Bl
#define SMEMB  (2 * BUFB)              // 147456 B (double buffer)

__device__ __forceinline__ void load_tile_async(
    const __nv_bfloat16* __restrict__ G, int ldk, int row0, int k0, uint32_t sm_tile)
{
    const int tid = threadIdx.x;
#pragma unroll
    for (int it = 0; it < 4; ++it) {
        int i = tid + it * 256;          // 1024 x 16B chunks
        int r = i >> 3;
        int s = i & 7;
        const void* src = G + (size_t)(row0 + r) * ldk + k0 + s * 8;
        uint32_t dst = sm_tile + (uint32_t)(r * RS + s * 8) * 2;
        cpasync16(dst, src);
    }
}

__global__ void __launch_bounds__(256, 1)
gemm_mma(const __nv_bfloat16* __restrict__ Ah, const __nv_bfloat16* __restrict__ Al,
         const __nv_bfloat16* __restrict__ Bh, const __nv_bfloat16* __restrict__ Bl,
         float* __restrict__ C, int M, int N, int K,
         const float* __restrict__ bias, int epi)
{
    extern __shared__ char smem[];
    const uint32_t sb = smem_u32(smem);
    const int tid = threadIdx.x;
    const int lane = tid & 31;
    const int wid = tid >> 5;
    const int warp_m = wid >> 1;       // 0..3
    const int warp_n = wid & 1;        // 0..1
    const int m0w = warp_m * 32;
    const int n0w = warp_n * 64;
    const int bx = blockIdx.x;         // N tile
    const int by = blockIdx.y;         // M tile
    const int arow = by * 128;
    const int brow = bx * 128;
    const int nchunk = K >> 6;

    // ldmatrix lane address offsets
    const int r_ = lane & 7, g = lane >> 3;
    const int aro = ((g & 1) << 3) + r_, ako = (g >> 1) << 3;   // A: m-row, k-col
    const int bro = ((g >> 1) << 3) + r_, bko = (g & 1) << 3;   // B: n-row, k-col

    float acc[2][8][4];
#pragma unroll
    for (int i = 0; i < 2; ++i)
#pragma unroll
        for (int j = 0; j < 8; ++j)
#pragma unroll
            for (int q = 0; q < 4; ++q) acc[i][j][q] = 0.0f;

    // prologue: chunk 0 -> buffer 0
    {
        uint32_t b0 = sb;
        load_tile_async(Ah, K, arow, 0, b0 + 0 * TILEB);
        load_tile_async(Al, K, arow, 0, b0 + 1 * TILEB);
        load_tile_async(Bh, K, brow, 0, b0 + 2 * TILEB);
        load_tile_async(Bl, K, brow, 0, b0 + 3 * TILEB);
        cp_commit();
    }

    for (int c = 0; c < nchunk; ++c) {
        if (c + 1 < nchunk) {
            uint32_t bb = sb + ((c + 1) & 1) * BUFB;
            const int k0 = (c + 1) << 6;
            load_tile_async(Ah, K, arow, k0, bb + 0 * TILEB);
            load_tile_async(Al, K, arow, k0, bb + 1 * TILEB);
            load_tile_async(Bh, K, brow, k0, bb + 2 * TILEB);
            load_tile_async(Bl, K, brow, k0, bb + 3 * TILEB);
            cp_commit();
            asm volatile("cp.async.wait_group 1;" ::: "memory");
        } else {
            asm volatile("cp.async.wait_group 0;" ::: "memory");
        }
        __syncthreads();

        const uint32_t bufb = sb + (c & 1) * BUFB;
        const uint32_t Ah_t = bufb + 0 * TILEB;
        const uint32_t Al_t = bufb + 1 * TILEB;
        const uint32_t Bh_t = bufb + 2 * TILEB;
        const uint32_t Bl_t = bufb + 3 * TILEB;

#pragma unroll
        for (int ks = 0; ks < 4; ++ks) {
            const int k0 = ks * 16;
            uint32_t ahf[2][4], alf[2][4];
#pragma unroll
            for (int mi = 0; mi < 2; ++mi) {
                uint32_t off = (uint32_t)((m0w + mi * 16 + aro) * RS + k0 + ako) * 2;
                ldsm4(ahf[mi], Ah_t + off);
                ldsm4(alf[mi], Al_t + off);
            }
            uint32_t bhf[4][4], blf[4][4];
#pragma unroll
            for (int nq = 0; nq < 4; ++nq) {
                uint32_t off = (uint32_t)((n0w + nq * 16 + bro) * RS + k0 + bko) * 2;
                ldsm4(bhf[nq], Bh_t + off);
                ldsm4(blf[nq], Bl_t + off);
            }
#pragma unroll
            for (int mi = 0; mi < 2; ++mi) {
#pragma unroll
                for (int nj = 0; nj < 8; ++nj) {
                    const uint32_t* bhp = &bhf[nj >> 1][(nj & 1) * 2];
                    const uint32_t* blp = &blf[nj >> 1][(nj & 1) * 2];
                    mma16816(acc[mi][nj], ahf[mi], bhp);   // Ah*Bh
                    mma16816(acc[mi][nj], ahf[mi], blp);   // Ah*Bl
                    mma16816(acc[mi][nj], alf[mi], bhp);   // Al*Bh
                }
            }
        }
        __syncthreads();
    }

    // epilogue: write C fragments
    const int rq = lane >> 2;          // 0..7
    const int cq = (lane & 3) * 2;     // 0,2,4,6
#pragma unroll
    for (int mi = 0; mi < 2; ++mi) {
        const int gm = arow + m0w + mi * 16;
#pragma unroll
        for (int nj = 0; nj < 8; ++nj) {
            const int gn = brow + n0w + nj * 8 + cq;
            float v0 = acc[mi][nj][0], v1 = acc[mi][nj][1];
            float v2 = acc[mi][nj][2], v3 = acc[mi][nj][3];
            if (epi == 1) {
                float b0 = __ldg(bias + gn), b1 = __ldg(bias + gn + 1);
                v0 = fast_softplus(v0 + b0);
                v1 = fast_softplus(v1 + b1);
                v2 = fast_softplus(v2 + b0);
                v3 = fast_softplus(v3 + b1);
            }
            *(float2*)(C + (size_t)(gm + rq) * N + gn)     = make_float2(v0, v1);
            *(float2*)(C + (size_t)(gm + 8 + rq) * N + gn) = make_float2(v2, v3);
        }
    }
}

// ---------------- fp32 -> (bf16 hi, bf16 lo) split ---------------------------
__global__ void __launch_bounds__(256)
cvt_split(const float* __restrict__ s, __nv_bfloat16* __restrict__ h,
          __nv_bfloat16* __restrict__ l, int n)
{
    int i = (blockIdx.x * 256 + threadIdx.x) * 4;
    if (i < n) {
        float4 v = *(const float4*)(s + i);
        __nv_bfloat162 h0 = __floats2bfloat162_rn(v.x, v.y);
        __nv_bfloat162 h1 = __floats2bfloat162_rn(v.z, v.w);
        *(__nv_bfloat162*)(h + i)     = h0;
        *(__nv_bfloat162*)(h + i + 2) = h1;
        float2 f0 = __bfloat1622float2(h0);
        float2 f1 = __bfloat1622float2(h1);
        *(__nv_bfloat162*)(l + i)     = __floats2bfloat162_rn(v.x - f0.x, v.y - f0.y);
        *(__nv_bfloat162*)(l + i + 2) = __floats2bfloat162_rn(v.z - f1.x, v.w - f1.y);
    }
}

// ---------------- depthwise causal conv1d (k=4) + SiLU -----------------------
__global__ void __launch_bounds__(256)
conv_silu_kernel(const float* __restrict__ conv_w, const float* __restrict__ conv_b)
{
    int idx = blockIdx.x * blockDim.x + threadIdx.x;   // over MROWS*DINNER
    int d = idx & (DINNER - 1);
    int row = idx >> 11;            // b*L + t
    int t = row & (LEN - 1);

    float acc = conv_b[d];
    const float* w = conv_w + d * DCONV;
#pragma unroll
    for (int j = 0; j < DCONV; ++j) {
        int tt = t - (DCONV - 1) + j;
        if (tt >= 0)
            acc = fmaf(g_xz[(size_t)(row - (DCONV - 1) + j) * N_XZ + d], w[j], acc);
    }
    g_xact[idx] = acc * fast_sigmoid(acc);
}

// ---------------- selective scan + gating ------------------------------------
__global__ void __launch_bounds__(256)
scan_kernel(const float* __restrict__ A_log, const float* __restrict__ Dp)
{
    const int lane16 = threadIdx.x & 15;           // state index s
    const int grp = threadIdx.x >> 4;              // channel group in block
    const int c = blockIdx.x * 16 + grp;           // 0..4095
    const int b = c >> 11;
    const int d = c & (DINNER - 1);

    const float a = -__expf(A_log[d * DSTATE + lane16]) * LOG2E;
    const float dp = Dp[d];

    const size_t base = (size_t)(b * LEN) * DINNER + d;
    const size_t zbase = (size_t)(b * LEN) * N_XZ + DINNER + d;

    float h = 0.0f;
    float dt = g_dt[base];
    float xv = g_xact[base];

    for (int t = 0; t < LEN; ++t) {
        int tn = (t + 1 < LEN) ? (t + 1) : t;
        float dt_n = g_dt[base + (size_t)tn * DINNER];
        float xv_n = g_xact[base + (size_t)tn * DINNER];

        float dA = fexp2(dt * a);
        h = fmaf(dA, h, dt * xv);

        float s = h;
        s += __shfl_xor_sync(0xffffffffu, s, 1);
        s += __shfl_xor_sync(0xffffffffu, s, 2);
        s += __shfl_xor_sync(0xffffffffu, s, 4);
        s += __shfl_xor_sync(0xffffffffu, s, 8);

        if (lane16 == 0) {
            float y = s + dp * xv;
            float z = g_xz[zbase + (size_t)t * N_XZ];
            g_yg[base + (size_t)t * DINNER] = y * (z * fast_sigmoid(z));
        }
        dt = dt_n;
        xv = xv_n;
    }
}

// ---------------- launch ------------------------------------------------------
extern "C" void kernel_launch(void* const* d_in, const int* in_sizes, int n_in,
                              void* d_out, int out_size)
{
    const float* x      = (const float*)d_in[0];   // [2,2048,1024]
    const float* W_in   = (const float*)d_in[1];   // [4096,1024]
    const float* conv_w = (const float*)d_in[2];   // [2048,1,4]
    const float* conv_b = (const float*)d_in[3];   // [2048]
    const float* A_log  = (const float*)d_in[4];   // [2048,16]
    const float* Dp     = (const float*)d_in[5];   // [2048]
    const float* W_dt   = (const float*)d_in[6];   // [2048,2048]
    const float* b_dt   = (const float*)d_in[7];   // [2048]
    const float* W_out  = (const float*)d_in[8];   // [1024,2048]
    float* out = (float*)d_out;                    // [2,2048,1024]

    float* xz = nullptr;  cudaGetSymbolAddress((void**)&xz, g_xz);
    float* xa = nullptr;  cudaGetSymbolAddress((void**)&xa, g_xact);
    float* dt = nullptr;  cudaGetSymbolAddress((void**)&dt, g_dt);
    float* yg = nullptr;  cudaGetSymbolAddress((void**)&yg, g_yg);

    __nv_bfloat16 *xh, *xl, *wih, *wil, *xah, *xal, *wdh, *wdl, *ygh, *ygl, *woh, *wol;
    cudaGetSymbolAddress((void**)&xh,  g_xh);  cudaGetSymbolAddress((void**)&xl,  g_xl);
    cudaGetSymbolAddress((void**)&wih, g_wih); cudaGetSymbolAddress((void**)&wil, g_wil);
    cudaGetSymbolAddress((void**)&xah, g_xah); cudaGetSymbolAddress((void**)&xal, g_xal);
    cudaGetSymbolAddress((void**)&wdh, g_wdh); cudaGetSymbolAddress((void**)&wdl, g_wdl);
    cudaGetSymbolAddress((void**)&ygh, g_ygh); cudaGetSymbolAddress((void**)&ygl, g_ygl);
    cudaGetSymbolAddress((void**)&woh, g_woh); cudaGetSymbolAddress((void**)&wol, g_wol);

    cudaFuncSetAttribute(gemm_mma, cudaFuncAttributeMaxDynamicSharedMemorySize, SMEMB);

    // 0) split conversions for GEMM1
    cvt_split<<<(MROWS * DMODEL) / 1024, 256>>>(x, xh, xl, MROWS * DMODEL);
    cvt_split<<<(N_XZ * DMODEL) / 1024, 256>>>(W_in, wih, wil, N_XZ * DMODEL);

    // 1) xz = x @ W_in^T   [4096,1024] x [4096,1024]^T -> [4096,4096]
    {
        dim3 grid(N_XZ / 128, MROWS / 128);
        gemm_mma<<<grid, 256, SMEMB>>>(xh, xl, wih, wil, xz,
                                       MROWS, N_XZ, DMODEL, nullptr, 0);
    }
    // 2) depthwise conv + SiLU -> g_xact
    conv_silu_kernel<<<(MROWS * DINNER) / 256, 256>>>(conv_w, conv_b);

    // 3) dt = softplus(x_act @ W_dt^T + b_dt) -> g_dt
    cvt_split<<<(MROWS * DINNER) / 1024, 256>>>(xa, xah, xal, MROWS * DINNER);
    cvt_split<<<(DINNER * DINNER) / 1024, 256>>>(W_dt, wdh, wdl, DINNER * DINNER);
    {
        dim3 grid(DINNER / 128, MROWS / 128);
        gemm_mma<<<grid, 256, SMEMB>>>(xah, xal, wdh, wdl, dt,
                                       MROWS, DINNER, DINNER, b_dt, 1);
    }
    // 4) selective scan + gate -> g_yg
    scan_kernel<<<(BSZ * DINNER) / 16, 256>>>(A_log, Dp);

    // 5) out = y_gated @ W_out^T   [4096,2048] x [1024,2048]^T -> [4096,1024]
    cvt_split<<<(MROWS * DINNER) / 1024, 256>>>(yg, ygh, ygl, MROWS * DINNER);
    cvt_split<<<(DMODEL * DINNER) / 1024, 256>>>(W_out, woh, wol, DMODEL * DINNER);
    {
        dim3 grid(DMODEL / 128, MROWS / 128);
        gemm_mma<<<grid, 256, SMEMB>>>(ygh, ygl, woh, wol, out,
                                       MROWS, DMODEL, DINNER, nullptr, 0);
    }
}

// round 11
// speedup vs baseline: 3.8270x; 1.5992x over previous
#include <cuda_runtime.h>
#include <cuda_bf16.h>
#include <cstdint>

// Problem dims (fixed)
#define BSZ      2
#define LEN      2048
#define DMODEL   1024
#define DSTATE   16
#define DCONV    4
#define DINNER   2048
#define MROWS    (BSZ * LEN)          // 4096
#define N_XZ     (2 * DINNER)         // 4096

// ---------------- scratch (device globals; no allocs allowed) ----------------
__device__ float g_xz[(size_t)MROWS * N_XZ];       // [4096, 4096]  x_proj | z
__device__ float g_xact[(size_t)MROWS * DINNER];   // [4096, 2048]
__device__ float g_dt[(size_t)MROWS * DINNER];     // [4096, 2048]
__device__ float g_yg[(size_t)MROWS * DINNER];     // [4096, 2048]

// bf16 hi/lo split buffers for tensor-core GEMMs
__device__ __nv_bfloat16 g_xh[(size_t)MROWS * DMODEL],  g_xl[(size_t)MROWS * DMODEL];
__device__ __nv_bfloat16 g_wih[(size_t)N_XZ * DMODEL],  g_wil[(size_t)N_XZ * DMODEL];
__device__ __nv_bfloat16 g_xah[(size_t)MROWS * DINNER], g_xal[(size_t)MROWS * DINNER];
__device__ __nv_bfloat16 g_wdh[(size_t)DINNER * DINNER],g_wdl[(size_t)DINNER * DINNER];
__device__ __nv_bfloat16 g_ygh[(size_t)MROWS * DINNER], g_ygl[(size_t)MROWS * DINNER];
__device__ __nv_bfloat16 g_woh[(size_t)DMODEL * DINNER],g_wol[(size_t)DMODEL * DINNER];

// ---------------- fast math helpers (FMA-pipe exp2, avoid MUFU storms) -------
__device__ __forceinline__ float fexp2(float x) {
    x = fminf(fmaxf(x, -125.0f), 125.0f);
    float r = rintf(x);
    float f = x - r;
    float p = 1.5403530e-4f;
    p = fmaf(p, f, 1.3333558e-3f);
    p = fmaf(p, f, 9.6181291e-3f);
    p = fmaf(p, f, 5.5504109e-2f);
    p = fmaf(p, f, 2.4022651e-1f);
    p = fmaf(p, f, 6.9314718e-1f);
    p = fmaf(p, f, 1.0f);
    int ir = (int)r;
    float sc = __int_as_float((ir + 127) << 23);
    return p * sc;
}
#define LOG2E 1.44269504f

__device__ __forceinline__ float fast_sigmoid(float x) {
    float e = fexp2(-x * LOG2E);
    return __fdividef(1.0f, 1.0f + e);
}
__device__ __forceinline__ float fast_softplus(float v) {
    float e = fexp2(-fabsf(v) * LOG2E);
    return fmaxf(v, 0.0f) + __logf(1.0f + e);
}

// ---------------- generic-PTX tensor helpers (sm_80+, compiles on compute_103)
__device__ __forceinline__ uint32_t smem_u32(const void* p) {
    uint32_t a;
    asm("{ .reg .u64 t; cvta.to.shared.u64 t, %1; cvt.u32.u64 %0, t; }" : "=r"(a) : "l"(p));
    return a;
}
__device__ __forceinline__ void cpasync16(uint32_t dst, const void* src) {
    asm volatile("cp.async.cg.shared.global [%0], [%1], 16;" :: "r"(dst), "l"(src));
}
__device__ __forceinline__ void cp_commit() {
    asm volatile("cp.async.commit_group;" ::: "memory");
}
__device__ __forceinline__ void ldsm4(uint32_t* r, uint32_t addr) {
    asm volatile("ldmatrix.sync.aligned.m8n8.x4.shared.b16 {%0,%1,%2,%3}, [%4];"
                 : "=r"(r[0]), "=r"(r[1]), "=r"(r[2]), "=r"(r[3]) : "r"(addr));
}
__device__ __forceinline__ void mma16816(float* c, const uint32_t* a, const uint32_t* b) {
    asm volatile(
        "mma.sync.aligned.m16n8k16.row.col.f32.bf16.bf16.f32 "
        "{%0,%1,%2,%3}, {%4,%5,%6,%7}, {%8,%9}, {%0,%1,%2,%3};"
        : "+f"(c[0]), "+f"(c[1]), "+f"(c[2]), "+f"(c[3])
        : "r"(a[0]), "r"(a[1]), "r"(a[2]), "r"(a[3]), "r"(b[0]), "r"(b[1]));
}

// ---------------- bf16-split HMMA GEMM ---------------------------------------
// C[M,N] = A[M,K] @ B[N,K]^T with A = Ah+Al, B = Bh+Bl (bf16 pairs), fp32 acc.
// CTA tile 128x128, K chunk 64, 16 warps (4m x 4n), warp tile 32x32.
// epi: 0 = plain store, 1 = softplus(acc + bias[n]).
#define RS     72                      // smem row stride in bf16 (padded, 144B)
#define TILEB  (128 * RS * 2)          // 18432 B per tile
#define BUFB   (4 * TILEB)             // Ah, Al, Bh, Bl
#define SMEMB  (2 * BUFB)              // 147456 B (double buffer)
#define GTHREADS 512

__device__ __forceinline__ void load_tile_async(
    const __nv_bfloat16* __restrict__ G, int ldk, int row0, int k0, uint32_t sm_tile)
{
    const int tid = threadIdx.x;
#pragma unroll
    for (int it = 0; it < 2; ++it) {
        int i = tid + it * GTHREADS;     // 1024 x 16B chunks
        int r = i >> 3;
        int s = i & 7;
        const void* src = G + (size_t)(row0 + r) * ldk + k0 + s * 8;
        uint32_t dst = sm_tile + (uint32_t)(r * RS + s * 8) * 2;
        cpasync16(dst, src);
    }
}

__global__ void __launch_bounds__(GTHREADS, 1)
gemm_mma(const __nv_bfloat16* __restrict__ Ah, const __nv_bfloat16* __restrict__ Al,
         const __nv_bfloat16* __restrict__ Bh, const __nv_bfloat16* __restrict__ Bl,
         float* __restrict__ C, int M, int N, int K,
         const float* __restrict__ bias, int epi)
{
    extern __shared__ char smem[];
    const uint32_t sb = smem_u32(smem);
    const int tid = threadIdx.x;
    const int lane = tid & 31;
    const int wid = tid >> 5;
    const int warp_m = wid >> 2;       // 0..3
    const int warp_n = wid & 3;        // 0..3
    const int m0w = warp_m * 32;
    const int n0w = warp_n * 32;
    const int bx = blockIdx.x;         // N tile
    const int by = blockIdx.y;         // M tile
    const int arow = by * 128;
    const int brow = bx * 128;
    const int nchunk = K >> 6;

    // ldmatrix lane address offsets
    const int r_ = lane & 7, g = lane >> 3;
    const int aro = ((g & 1) << 3) + r_, ako = (g >> 1) << 3;   // A: m-row, k-col
    const int bro = ((g >> 1) << 3) + r_, bko = (g & 1) << 3;   // B: n-row, k-col

    float acc[2][4][4];
#pragma unroll
    for (int i = 0; i < 2; ++i)
#pragma unroll
        for (int j = 0; j < 4; ++j)
#pragma unroll
            for (int q = 0; q < 4; ++q) acc[i][j][q] = 0.0f;

    // prologue: chunk 0 -> buffer 0
    {
        uint32_t b0 = sb;
        load_tile_async(Ah, K, arow, 0, b0 + 0 * TILEB);
        load_tile_async(Al, K, arow, 0, b0 + 1 * TILEB);
        load_tile_async(Bh, K, brow, 0, b0 + 2 * TILEB);
        load_tile_async(Bl, K, brow, 0, b0 + 3 * TILEB);
        cp_commit();
    }

    for (int c = 0; c < nchunk; ++c) {
        if (c + 1 < nchunk) {
            uint32_t bb = sb + ((c + 1) & 1) * BUFB;
            const int k0 = (c + 1) << 6;
            load_tile_async(Ah, K, arow, k0, bb + 0 * TILEB);
            load_tile_async(Al, K, arow, k0, bb + 1 * TILEB);
            load_tile_async(Bh, K, brow, k0, bb + 2 * TILEB);
            load_tile_async(Bl, K, brow, k0, bb + 3 * TILEB);
            cp_commit();
            asm volatile("cp.async.wait_group 1;" ::: "memory");
        } else {
            asm volatile("cp.async.wait_group 0;" ::: "memory");
        }
        __syncthreads();

        const uint32_t bufb = sb + (c & 1) * BUFB;
        const uint32_t Ah_t = bufb + 0 * TILEB;
        const uint32_t Al_t = bufb + 1 * TILEB;
        const uint32_t Bh_t = bufb + 2 * TILEB;
        const uint32_t Bl_t = bufb + 3 * TILEB;

#pragma unroll
        for (int ks = 0; ks < 4; ++ks) {
            const int k0 = ks * 16;
            uint32_t ahf[2][4], alf[2][4];
#pragma unroll
            for (int mi = 0; mi < 2; ++mi) {
                uint32_t off = (uint32_t)((m0w + mi * 16 + aro) * RS + k0 + ako) * 2;
                ldsm4(ahf[mi], Ah_t + off);
                ldsm4(alf[mi], Al_t + off);
            }
            uint32_t bhf[2][4], blf[2][4];
#pragma unroll
            for (int nq = 0; nq < 2; ++nq) {
                uint32_t off = (uint32_t)((n0w + nq * 16 + bro) * RS + k0 + bko) * 2;
                ldsm4(bhf[nq], Bh_t + off);
                ldsm4(blf[nq], Bl_t + off);
            }
#pragma unroll
            for (int mi = 0; mi < 2; ++mi) {
#pragma unroll
                for (int nj = 0; nj < 4; ++nj) {
                    const uint32_t* bhp = &bhf[nj >> 1][(nj & 1) * 2];
                    const uint32_t* blp = &blf[nj >> 1][(nj & 1) * 2];
                    mma16816(acc[mi][nj], ahf[mi], bhp);   // Ah*Bh
                    mma16816(acc[mi][nj], ahf[mi], blp);   // Ah*Bl
                    mma16816(acc[mi][nj], alf[mi], bhp);   // Al*Bh
                }
            }
        }
        __syncthreads();
    }

    // epilogue: write C fragments
    const int rq = lane >> 2;          // 0..7
    const int cq = (lane & 3) * 2;     // 0,2,4,6
#pragma unroll
    for (int mi = 0; mi < 2; ++mi) {
        const int gm = arow + m0w + mi * 16;
#pragma unroll
        for (int nj = 0; nj < 4; ++nj) {
            const int gn = brow + n0w + nj * 8 + cq;
            float v0 = acc[mi][nj][0], v1 = acc[mi][nj][1];
            float v2 = acc[mi][nj][2], v3 = acc[mi][nj][3];
            if (epi == 1) {
                float b0 = __ldg(bias + gn), b1 = __ldg(bias + gn + 1);
                v0 = fast_softplus(v0 + b0);
                v1 = fast_softplus(v1 + b1);
                v2 = fast_softplus(v2 + b0);
                v3 = fast_softplus(v3 + b1);
            }
            *(float2*)(C + (size_t)(gm + rq) * N + gn)     = make_float2(v0, v1);
            *(float2*)(C + (size_t)(gm + 8 + rq) * N + gn) = make_float2(v2, v3);
        }
    }
}

// ---------------- fp32 -> (bf16 hi, bf16 lo) split ---------------------------
__global__ void __launch_bounds__(256)
cvt_split(const float* __restrict__ s, __nv_bfloat16* __restrict__ h,
          __nv_bfloat16* __restrict__ l, int n)
{
    int i = (blockIdx.x * 256 + threadIdx.x) * 4;
    if (i < n) {
        float4 v = *(const float4*)(s + i);
        __nv_bfloat162 h0 = __floats2bfloat162_rn(v.x, v.y);
        __nv_bfloat162 h1 = __floats2bfloat162_rn(v.z, v.w);
        *(__nv_bfloat162*)(h + i)     = h0;
        *(__nv_bfloat162*)(h + i + 2) = h1;
        float2 f0 = __bfloat1622float2(h0);
        float2 f1 = __bfloat1622float2(h1);
        *(__nv_bfloat162*)(l + i)     = __floats2bfloat162_rn(v.x - f0.x, v.y - f0.y);
        *(__nv_bfloat162*)(l + i + 2) = __floats2bfloat162_rn(v.z - f1.x, v.w - f1.y);
    }
}

// ---------------- depthwise causal conv1d (k=4) + SiLU -----------------------
__global__ void __launch_bounds__(256)
conv_silu_kernel(const float* __restrict__ conv_w, const float* __restrict__ conv_b)
{
    int idx = blockIdx.x * blockDim.x + threadIdx.x;   // over MROWS*DINNER
    int d = idx & (DINNER - 1);
    int row = idx >> 11;            // b*L + t
    int t = row & (LEN - 1);

    float acc = conv_b[d];
    const float* w = conv_w + d * DCONV;
#pragma unroll
    for (int j = 0; j < DCONV; ++j) {
        int tt = t - (DCONV - 1) + j;
        if (tt >= 0)
            acc = fmaf(g_xz[(size_t)(row - (DCONV - 1) + j) * N_XZ + d], w[j], acc);
    }
    g_xact[idx] = acc * fast_sigmoid(acc);
}

// ---------------- selective scan + gating (smem-tiled) ------------------------
// Block: 256 threads = 16 channels x 16 state-lanes. Tiles of 64 timesteps of
// (dt, x_act, z) are staged into smem with coalesced cooperative loads, so the
// recurrence runs entirely out of LDS (conflict-free broadcast) instead of
// stalling on 1-step-prefetched DRAM loads.
#define SCT 64                         // timesteps per tile
__global__ void __launch_bounds__(256)
scan_kernel(const float* __restrict__ A_log, const float* __restrict__ Dp)
{
    __shared__ float dt_s[SCT * 16];
    __shared__ float x_s[SCT * 16];
    __shared__ float z_s[SCT * 16];
    __shared__ float y_s[SCT * 16];

    const int tid = threadIdx.x;
    const int lane16 = tid & 15;           // state index s
    const int grp = tid >> 4;              // channel slot in block (0..15)
    const int b = blockIdx.x >> 7;         // 128 blocks per batch
    const int d0 = (blockIdx.x & 127) * 16;
    const int d = d0 + grp;

    const float a = -__expf(A_log[d * DSTATE + lane16]) * LOG2E;
    const float dp = Dp[d];

    const size_t rowbase = (size_t)(b * LEN);
    float h = 0.0f;

    for (int tile = 0; tile < LEN / SCT; ++tile) {
        const int t0 = tile * SCT;
        // cooperative loads: element e -> (t = e>>4, j = e&15)
#pragma unroll
        for (int it = 0; it < 4; ++it) {
            int e = tid + it * 256;
            int t = e >> 4, j = e & 15;
            size_t r = rowbase + t0 + t;
            dt_s[e] = g_dt[r * DINNER + d0 + j];
            x_s[e]  = g_xact[r * DINNER + d0 + j];
            z_s[e]  = g_xz[r * N_XZ + DINNER + d0 + j];
        }
        __syncthreads();

#pragma unroll 4
        for (int t = 0; t < SCT; ++t) {
            float dt = dt_s[t * 16 + grp];
            float xv = x_s[t * 16 + grp];
            float dA = fexp2(dt * a);
            h = fmaf(dA, h, dt * xv);

            float s = h;
            s += __shfl_xor_sync(0xffffffffu, s, 1);
            s += __shfl_xor_sync(0xffffffffu, s, 2);
            s += __shfl_xor_sync(0xffffffffu, s, 4);
            s += __shfl_xor_sync(0xffffffffu, s, 8);

            if (lane16 == 0) {
                float z = z_s[t * 16 + grp];
                y_s[t * 16 + grp] = (s + dp * xv) * (z * fast_sigmoid(z));
            }
        }
        __syncthreads();

        // cooperative coalesced store of the y tile
#pragma unroll
        for (int it = 0; it < 4; ++it) {
            int e = tid + it * 256;
            int t = e >> 4, j = e & 15;
            g_yg[(rowbase + t0 + t) * DINNER + d0 + j] = y_s[e];
        }
        __syncthreads();
    }
}

// ---------------- launch ------------------------------------------------------
extern "C" void kernel_launch(void* const* d_in, const int* in_sizes, int n_in,
                              void* d_out, int out_size)
{
    const float* x      = (const float*)d_in[0];   // [2,2048,1024]
    const float* W_in   = (const float*)d_in[1];   // [4096,1024]
    const float* conv_w = (const float*)d_in[2];   // [2048,1,4]
    const float* conv_b = (const float*)d_in[3];   // [2048]
    const float* A_log  = (const float*)d_in[4];   // [2048,16]
    const float* Dp     = (const float*)d_in[5];   // [2048]
    const float* W_dt   = (const float*)d_in[6];   // [2048,2048]
    const float* b_dt   = (const float*)d_in[7];   // [2048]
    const float* W_out  = (const float*)d_in[8];   // [1024,2048]
    float* out = (float*)d_out;                    // [2,2048,1024]

    float* xz = nullptr;  cudaGetSymbolAddress((void**)&xz, g_xz);
    float* xa = nullptr;  cudaGetSymbolAddress((void**)&xa, g_xact);
    float* dt = nullptr;  cudaGetSymbolAddress((void**)&dt, g_dt);
    float* yg = nullptr;  cudaGetSymbolAddress((void**)&yg, g_yg);

    __nv_bfloat16 *xh, *xl, *wih, *wil, *xah, *xal, *wdh, *wdl, *ygh, *ygl, *woh, *wol;
    cudaGetSymbolAddress((void**)&xh,  g_xh);  cudaGetSymbolAddress((void**)&xl,  g_xl);
    cudaGetSymbolAddress((void**)&wih, g_wih); cudaGetSymbolAddress((void**)&wil, g_wil);
    cudaGetSymbolAddress((void**)&xah, g_xah); cudaGetSymbolAddress((void**)&xal, g_xal);
    cudaGetSymbolAddress((void**)&wdh, g_wdh); cudaGetSymbolAddress((void**)&wdl, g_wdl);
    cudaGetSymbolAddress((void**)&ygh, g_ygh); cudaGetSymbolAddress((void**)&ygl, g_ygl);
    cudaGetSymbolAddress((void**)&woh, g_woh); cudaGetSymbolAddress((void**)&wol, g_wol);

    cudaFuncSetAttribute(gemm_mma, cudaFuncAttributeMaxDynamicSharedMemorySize, SMEMB);

    // 0) split conversions for GEMM1
    cvt_split<<<(MROWS * DMODEL) / 1024, 256>>>(x, xh, xl, MROWS * DMODEL);
    cvt_split<<<(N_XZ * DMODEL) / 1024, 256>>>(W_in, wih, wil, N_XZ * DMODEL);

    // 1) xz = x @ W_in^T   [4096,1024] x [4096,1024]^T -> [4096,4096]
    {
        dim3 grid(N_XZ / 128, MROWS / 128);
        gemm_mma<<<grid, GTHREADS, SMEMB>>>(xh, xl, wih, wil, xz,
                                            MROWS, N_XZ, DMODEL, nullptr, 0);
    }
    // 2) depthwise conv + SiLU -> g_xact
    conv_silu_kernel<<<(MROWS * DINNER) / 256, 256>>>(conv_w, conv_b);

    // 3) dt = softplus(x_act @ W_dt^T + b_dt) -> g_dt
    cvt_split<<<(MROWS * DINNER) / 1024, 256>>>(xa, xah, xal, MROWS * DINNER);
    cvt_split<<<(DINNER * DINNER) / 1024, 256>>>(W_dt, wdh, wdl, DINNER * DINNER);
    {
        dim3 grid(DINNER / 128, MROWS / 128);
        gemm_mma<<<grid, GTHREADS, SMEMB>>>(xah, xal, wdh, wdl, dt,
                                            MROWS, DINNER, DINNER, b_dt, 1);
    }
    // 4) selective scan + gate -> g_yg
    scan_kernel<<<BSZ * (DINNER / 16), 256>>>(A_log, Dp);

    // 5) out = y_gated @ W_out^T   [4096,2048] x [1024,2048]^T -> [4096,1024]
    cvt_split<<<(MROWS * DINNER) / 1024, 256>>>(yg, ygh, ygl, MROWS * DINNER);
    cvt_split<<<(DMODEL * DINNER) / 1024, 256>>>(W_out, woh, wol, DMODEL * DINNER);
    {
        dim3 grid(DMODEL / 128, MROWS / 128);
        gemm_mma<<<grid, GTHREADS, SMEMB>>>(ygh, ygl, woh, wol, out,
                                            MROWS, DMODEL, DINNER, nullptr, 0);
    }
}

// round 12
// speedup vs baseline: 4.0097x; 1.0477x over previous
#include <cuda_runtime.h>
#include <cuda_bf16.h>
#include <cstdint>

// Problem dims (fixed)
#define BSZ      2
#define LEN      2048
#define DMODEL   1024
#define DSTATE   16
#define DCONV    4
#define DINNER   2048
#define MROWS    (BSZ * LEN)          // 4096
#define N_XZ     (2 * DINNER)         // 4096

// ---------------- scratch (device globals; no allocs allowed) ----------------
__device__ float g_xz[(size_t)MROWS * N_XZ];       // [4096, 4096]  x_proj | z
__device__ float g_dt[(size_t)MROWS * DINNER];     // [4096, 2048]

// bf16 hi/lo split buffers for tensor-core GEMMs
__device__ __nv_bfloat16 g_xh[(size_t)MROWS * DMODEL],  g_xl[(size_t)MROWS * DMODEL];
__device__ __nv_bfloat16 g_wih[(size_t)N_XZ * DMODEL],  g_wil[(size_t)N_XZ * DMODEL];
__device__ __nv_bfloat16 g_xah[(size_t)MROWS * DINNER], g_xal[(size_t)MROWS * DINNER];
__device__ __nv_bfloat16 g_wdh[(size_t)DINNER * DINNER],g_wdl[(size_t)DINNER * DINNER];
__device__ __nv_bfloat16 g_ygh[(size_t)MROWS * DINNER], g_ygl[(size_t)MROWS * DINNER];
__device__ __nv_bfloat16 g_woh[(size_t)DMODEL * DINNER],g_wol[(size_t)DMODEL * DINNER];

// ---------------- fast math helpers (FMA-pipe exp2, avoid MUFU storms) -------
__device__ __forceinline__ float fexp2(float x) {
    x = fminf(fmaxf(x, -125.0f), 125.0f);
    float r = rintf(x);
    float f = x - r;
    float p = 1.5403530e-4f;
    p = fmaf(p, f, 1.3333558e-3f);
    p = fmaf(p, f, 9.6181291e-3f);
    p = fmaf(p, f, 5.5504109e-2f);
    p = fmaf(p, f, 2.4022651e-1f);
    p = fmaf(p, f, 6.9314718e-1f);
    p = fmaf(p, f, 1.0f);
    int ir = (int)r;
    float sc = __int_as_float((ir + 127) << 23);
    return p * sc;
}
#define LOG2E 1.44269504f

__device__ __forceinline__ float fast_sigmoid(float x) {
    float e = fexp2(-x * LOG2E);
    return __fdividef(1.0f, 1.0f + e);
}
__device__ __forceinline__ float fast_softplus(float v) {
    float e = fexp2(-fabsf(v) * LOG2E);
    return fmaxf(v, 0.0f) + __logf(1.0f + e);
}

// ---------------- generic-PTX tensor helpers (sm_80+, compiles on compute_103)
__device__ __forceinline__ uint32_t smem_u32(const void* p) {
    uint32_t a;
    asm("{ .reg .u64 t; cvta.to.shared.u64 t, %1; cvt.u32.u64 %0, t; }" : "=r"(a) : "l"(p));
    return a;
}
__device__ __forceinline__ void cpasync16(uint32_t dst, const void* src) {
    asm volatile("cp.async.cg.shared.global [%0], [%1], 16;" :: "r"(dst), "l"(src));
}
__device__ __forceinline__ void cp_commit() {
    asm volatile("cp.async.commit_group;" ::: "memory");
}
__device__ __forceinline__ void ldsm4(uint32_t* r, uint32_t addr) {
    asm volatile("ldmatrix.sync.aligned.m8n8.x4.shared.b16 {%0,%1,%2,%3}, [%4];"
                 : "=r"(r[0]), "=r"(r[1]), "=r"(r[2]), "=r"(r[3]) : "r"(addr));
}
// NOTE: non-volatile — pure register op; lets ptxas schedule/pipeline HMMA and
// avoids the forced program-order RAW chains on accumulators.
__device__ __forceinline__ void mma16816(float* c, const uint32_t* a, const uint32_t* b) {
    asm("mma.sync.aligned.m16n8k16.row.col.f32.bf16.bf16.f32 "
        "{%0,%1,%2,%3}, {%4,%5,%6,%7}, {%8,%9}, {%0,%1,%2,%3};"
        : "+f"(c[0]), "+f"(c[1]), "+f"(c[2]), "+f"(c[3])
        : "r"(a[0]), "r"(a[1]), "r"(a[2]), "r"(a[3]), "r"(b[0]), "r"(b[1]));
}

// ---------------- bf16-split HMMA GEMM ---------------------------------------
// C[M,N] = A[M,K] @ B[N,K]^T with A = Ah+Al, B = Bh+Bl (bf16 pairs), fp32 acc.
// CTA tile 128x128, K chunk 64, 16 warps (4m x 4n), warp tile 32x32.
// 3-stage cp.async ring, one barrier per chunk, pass-major MMA ordering.
// epi: 0 = plain store, 1 = softplus(acc + bias[n]).
#define RS     72                      // smem row stride in bf16 (padded, 144B)
#define TILEB  (128 * RS * 2)          // 18432 B per tile
#define BUFB   (4 * TILEB)             // Ah, Al, Bh, Bl
#define NSTAGE 3
#define SMEMB  (NSTAGE * BUFB)         // 221184 B
#define GTHREADS 512

__device__ __forceinline__ void load_tile_async(
    const __nv_bfloat16* __restrict__ G, int ldk, int row0, int k0, uint32_t sm_tile)
{
    const int tid = threadIdx.x;
#pragma unroll
    for (int it = 0; it < 2; ++it) {
        int i = tid + it * GTHREADS;     // 1024 x 16B chunks
        int r = i >> 3;
        int s = i & 7;
        const void* src = G + (size_t)(row0 + r) * ldk + k0 + s * 8;
        uint32_t dst = sm_tile + (uint32_t)(r * RS + s * 8) * 2;
        cpasync16(dst, src);
    }
}

__device__ __forceinline__ void load_chunk(
    const __nv_bfloat16* Ah, const __nv_bfloat16* Al,
    const __nv_bfloat16* Bh, const __nv_bfloat16* Bl,
    int K, int arow, int brow, int k0, uint32_t stage_base)
{
    load_tile_async(Ah, K, arow, k0, stage_base + 0 * TILEB);
    load_tile_async(Al, K, arow, k0, stage_base + 1 * TILEB);
    load_tile_async(Bh, K, brow, k0, stage_base + 2 * TILEB);
    load_tile_async(Bl, K, brow, k0, stage_base + 3 * TILEB);
}

__global__ void __launch_bounds__(GTHREADS, 1)
gemm_mma(const __nv_bfloat16* __restrict__ Ah, const __nv_bfloat16* __restrict__ Al,
         const __nv_bfloat16* __restrict__ Bh, const __nv_bfloat16* __restrict__ Bl,
         float* __restrict__ C, int M, int N, int K,
         const float* __restrict__ bias, int epi)
{
    extern __shared__ char smem[];
    const uint32_t sb = smem_u32(smem);
    const int tid = threadIdx.x;
    const int lane = tid & 31;
    const int wid = tid >> 5;
    const int warp_m = wid >> 2;       // 0..3
    const int warp_n = wid & 3;        // 0..3
    const int m0w = warp_m * 32;
    const int n0w = warp_n * 32;
    const int bx = blockIdx.x;         // N tile
    const int by = blockIdx.y;         // M tile
    const int arow = by * 128;
    const int brow = bx * 128;
    const int nchunk = K >> 6;

    // ldmatrix lane address offsets
    const int r_ = lane & 7, g = lane >> 3;
    const int aro = ((g & 1) << 3) + r_, ako = (g >> 1) << 3;   // A: m-row, k-col
    const int bro = ((g >> 1) << 3) + r_, bko = (g & 1) << 3;   // B: n-row, k-col

    float acc[2][4][4];
#pragma unroll
    for (int i = 0; i < 2; ++i)
#pragma unroll
        for (int j = 0; j < 4; ++j)
#pragma unroll
            for (int q = 0; q < 4; ++q) acc[i][j][q] = 0.0f;

    // prologue: chunks 0 and 1 into stages 0 and 1
    load_chunk(Ah, Al, Bh, Bl, K, arow, brow, 0, sb);
    cp_commit();
    if (1 < nchunk) load_chunk(Ah, Al, Bh, Bl, K, arow, brow, 64, sb + BUFB);
    cp_commit();

    int stage = 0;          // stage holding chunk c
    int lstage = 2 % NSTAGE; // stage to load chunk c+2 into

    for (int c = 0; c < nchunk; ++c) {
        asm volatile("cp.async.wait_group 1;" ::: "memory");
        __syncthreads();   // all warps: chunk c visible AND chunk c-1 compute done

        // issue loads for chunk c+2 into the stage freed by chunk c-1
        if (c + 2 < nchunk)
            load_chunk(Ah, Al, Bh, Bl, K, arow, brow, (c + 2) << 6, sb + lstage * BUFB);
        cp_commit();

        const uint32_t bufb = sb + stage * BUFB;
        const uint32_t Ah_t = bufb + 0 * TILEB;
        const uint32_t Al_t = bufb + 1 * TILEB;
        const uint32_t Bh_t = bufb + 2 * TILEB;
        const uint32_t Bl_t = bufb + 3 * TILEB;

#pragma unroll
        for (int ks = 0; ks < 4; ++ks) {
            const int k0 = ks * 16;
            uint32_t ahf[2][4], alf[2][4];
#pragma unroll
            for (int mi = 0; mi < 2; ++mi) {
                uint32_t off = (uint32_t)((m0w + mi * 16 + aro) * RS + k0 + ako) * 2;
                ldsm4(ahf[mi], Ah_t + off);
                ldsm4(alf[mi], Al_t + off);
            }
            uint32_t bhf[2][4], blf[2][4];
#pragma unroll
            for (int nq = 0; nq < 2; ++nq) {
                uint32_t off = (uint32_t)((n0w + nq * 16 + bro) * RS + k0 + bko) * 2;
                ldsm4(bhf[nq], Bh_t + off);
                ldsm4(blf[nq], Bl_t + off);
            }
            // pass-major ordering: 8 independent accumulators between reuses
#pragma unroll
            for (int mi = 0; mi < 2; ++mi)
#pragma unroll
                for (int nj = 0; nj < 4; ++nj)
                    mma16816(acc[mi][nj], ahf[mi], &bhf[nj >> 1][(nj & 1) * 2]);
#pragma unroll
            for (int mi = 0; mi < 2; ++mi)
#pragma unroll
                for (int nj = 0; nj < 4; ++nj)
                    mma16816(acc[mi][nj], ahf[mi], &blf[nj >> 1][(nj & 1) * 2]);
#pragma unroll
            for (int mi = 0; mi < 2; ++mi)
#pragma unroll
                for (int nj = 0; nj < 4; ++nj)
                    mma16816(acc[mi][nj], alf[mi], &bhf[nj >> 1][(nj & 1) * 2]);
        }

        stage = (stage + 1 < NSTAGE) ? stage + 1 : 0;
        lstage = (lstage + 1 < NSTAGE) ? lstage + 1 : 0;
    }

    // epilogue: write C fragments
    const int rq = lane >> 2;          // 0..7
    const int cq = (lane & 3) * 2;     // 0,2,4,6
#pragma unroll
    for (int mi = 0; mi < 2; ++mi) {
        const int gm = arow + m0w + mi * 16;
#pragma unroll
        for (int nj = 0; nj < 4; ++nj) {
            const int gn = brow + n0w + nj * 8 + cq;
            float v0 = acc[mi][nj][0], v1 = acc[mi][nj][1];
            float v2 = acc[mi][nj][2], v3 = acc[mi][nj][3];
            if (epi == 1) {
                float b0 = __ldg(bias + gn), b1 = __ldg(bias + gn + 1);
                v0 = fast_softplus(v0 + b0);
                v1 = fast_softplus(v1 + b1);
                v2 = fast_softplus(v2 + b0);
                v3 = fast_softplus(v3 + b1);
            }
            *(float2*)(C + (size_t)(gm + rq) * N + gn)     = make_float2(v0, v1);
            *(float2*)(C + (size_t)(gm + 8 + rq) * N + gn) = make_float2(v2, v3);
        }
    }
}

// ---------------- fp32 -> (bf16 hi, bf16 lo) split ---------------------------
__global__ void __launch_bounds__(256)
cvt_split(const float* __restrict__ s, __nv_bfloat16* __restrict__ h,
          __nv_bfloat16* __restrict__ l, int n)
{
    int i = (blockIdx.x * 256 + threadIdx.x) * 4;
    if (i < n) {
        float4 v = *(const float4*)(s + i);
        __nv_bfloat162 h0 = __floats2bfloat162_rn(v.x, v.y);
        __nv_bfloat162 h1 = __floats2bfloat162_rn(v.z, v.w);
        *(__nv_bfloat162*)(h + i)     = h0;
        *(__nv_bfloat162*)(h + i + 2) = h1;
        float2 f0 = __bfloat1622float2(h0);
        float2 f1 = __bfloat1622float2(h1);
        *(__nv_bfloat162*)(l + i)     = __floats2bfloat162_rn(v.x - f0.x, v.y - f0.y);
        *(__nv_bfloat162*)(l + i + 2) = __floats2bfloat162_rn(v.z - f1.x, v.w - f1.y);
    }
}

// ---------------- depthwise causal conv1d (k=4) + SiLU -> split bf16 ---------
__global__ void __launch_bounds__(256)
conv_silu_kernel(const float* __restrict__ conv_w, const float* __restrict__ conv_b)
{
    int idx = blockIdx.x * blockDim.x + threadIdx.x;   // over MROWS*DINNER
    int d = idx & (DINNER - 1);
    int row = idx >> 11;            // b*L + t
    int t = row & (LEN - 1);

    float acc = conv_b[d];
    const float* w = conv_w + d * DCONV;
#pragma unroll
    for (int j = 0; j < DCONV; ++j) {
        int tt = t - (DCONV - 1) + j;
        if (tt >= 0)
            acc = fmaf(g_xz[(size_t)(row - (DCONV - 1) + j) * N_XZ + d], w[j], acc);
    }
    float v = acc * fast_sigmoid(acc);
    __nv_bfloat16 hi = __float2bfloat16(v);
    g_xah[idx] = hi;
    g_xal[idx] = __float2bfloat16(v - __bfloat162float(hi));
}

// ---------------- selective scan + gating (smem-tiled) ------------------------
// Block: 256 threads = 16 channels x 16 state-lanes. Tiles of 64 timesteps of
// (dt, x_act, z) staged into smem with coalesced loads; recurrence runs from
// LDS. x_act is reconstructed from its bf16 hi/lo split; y is written directly
// as bf16 hi/lo split for GEMM3.
#define SCT 64                         // timesteps per tile
__global__ void __launch_bounds__(256)
scan_kernel(const float* __restrict__ A_log, const float* __restrict__ Dp)
{
    __shared__ float dt_s[SCT * 16];
    __shared__ float x_s[SCT * 16];
    __shared__ float z_s[SCT * 16];
    __shared__ float y_s[SCT * 16];

    const int tid = threadIdx.x;
    const int lane16 = tid & 15;           // state index s
    const int grp = tid >> 4;              // channel slot in block (0..15)
    const int b = blockIdx.x >> 7;         // 128 blocks per batch
    const int d0 = (blockIdx.x & 127) * 16;
    const int d = d0 + grp;

    const float a = -__expf(A_log[d * DSTATE + lane16]) * LOG2E;
    const float dp = Dp[d];

    const size_t rowbase = (size_t)(b * LEN);
    float h = 0.0f;

    for (int tile = 0; tile < LEN / SCT; ++tile) {
        const int t0 = tile * SCT;
        // cooperative loads: element e -> (t = e>>4, j = e&15)
#pragma unroll
        for (int it = 0; it < 4; ++it) {
            int e = tid + it * 256;
            int t = e >> 4, j = e & 15;
            size_t r = rowbase + t0 + t;
            size_t di = r * DINNER + d0 + j;
            dt_s[e] = g_dt[di];
            x_s[e]  = __bfloat162float(g_xah[di]) + __bfloat162float(g_xal[di]);
            z_s[e]  = g_xz[r * N_XZ + DINNER + d0 + j];
        }
        __syncthreads();

#pragma unroll 4
        for (int t = 0; t < SCT; ++t) {
            float dt = dt_s[t * 16 + grp];
            float xv = x_s[t * 16 + grp];
            float dA = fexp2(dt * a);
            h = fmaf(dA, h, dt * xv);

            float s = h;
            s += __shfl_xor_sync(0xffffffffu, s, 1);
            s += __shfl_xor_sync(0xffffffffu, s, 2);
            s += __shfl_xor_sync(0xffffffffu, s, 4);
            s += __shfl_xor_sync(0xffffffffu, s, 8);

            if (lane16 == 0) {
                float z = z_s[t * 16 + grp];
                y_s[t * 16 + grp] = (s + dp * xv) * (z * fast_sigmoid(z));
            }
        }
        __syncthreads();

        // cooperative store of the y tile, split to bf16 hi/lo
#pragma unroll
        for (int it = 0; it < 4; ++it) {
            int e = tid + it * 256;
            int t = e >> 4, j = e & 15;
            float y = y_s[e];
            __nv_bfloat16 hi = __float2bfloat16(y);
            size_t di = (rowbase + t0 + t) * DINNER + d0 + j;
            g_ygh[di] = hi;
            g_ygl[di] = __float2bfloat16(y - __bfloat162float(hi));
        }
        __syncthreads();
    }
}

// ---------------- launch ------------------------------------------------------
extern "C" void kernel_launch(void* const* d_in, const int* in_sizes, int n_in,
                              void* d_out, int out_size)
{
    const float* x      = (const float*)d_in[0];   // [2,2048,1024]
    const float* W_in   = (const float*)d_in[1];   // [4096,1024]
    const float* conv_w = (const float*)d_in[2];   // [2048,1,4]
    const float* conv_b = (const float*)d_in[3];   // [2048]
    const float* A_log  = (const float*)d_in[4];   // [2048,16]
    const float* Dp     = (const float*)d_in[5];   // [2048]
    const float* W_dt   = (const float*)d_in[6];   // [2048,2048]
    const float* b_dt   = (const float*)d_in[7];   // [2048]
    const float* W_out  = (const float*)d_in[8];   // [1024,2048]
    float* out = (float*)d_out;                    // [2,2048,1024]

    float* xz = nullptr;  cudaGetSymbolAddress((void**)&xz, g_xz);
    float* dt = nullptr;  cudaGetSymbolAddress((void**)&dt, g_dt);

    __nv_bfloat16 *xh, *xl, *wih, *wil, *xah, *xal, *wdh, *wdl, *ygh, *ygl, *woh, *wol;
    cudaGetSymbolAddress((void**)&xh,  g_xh);  cudaGetSymbolAddress((void**)&xl,  g_xl);
    cudaGetSymbolAddress((void**)&wih, g_wih); cudaGetSymbolAddress((void**)&wil, g_wil);
    cudaGetSymbolAddress((void**)&xah, g_xah); cudaGetSymbolAddress((void**)&xal, g_xal);
    cudaGetSymbolAddress((void**)&wdh, g_wdh); cudaGetSymbolAddress((void**)&wdl, g_wdl);
    cudaGetSymbolAddress((void**)&ygh, g_ygh); cudaGetSymbolAddress((void**)&ygl, g_ygl);
    cudaGetSymbolAddress((void**)&woh, g_woh); cudaGetSymbolAddress((void**)&wol, g_wol);

    cudaFuncSetAttribute(gemm_mma, cudaFuncAttributeMaxDynamicSharedMemorySize, SMEMB);

    // 0) split conversions (inputs + weights)
    cvt_split<<<(MROWS * DMODEL) / 1024, 256>>>(x, xh, xl, MROWS * DMODEL);
    cvt_split<<<(N_XZ * DMODEL) / 1024, 256>>>(W_in, wih, wil, N_XZ * DMODEL);
    cvt_split<<<(DINNER * DINNER) / 1024, 256>>>(W_dt, wdh, wdl, DINNER * DINNER);
    cvt_split<<<(DMODEL * DINNER) / 1024, 256>>>(W_out, woh, wol, DMODEL * DINNER);

    // 1) xz = x @ W_in^T   [4096,1024] x [4096,1024]^T -> [4096,4096]
    {
        dim3 grid(N_XZ / 128, MROWS / 128);
        gemm_mma<<<grid, GTHREADS, SMEMB>>>(xh, xl, wih, wil, xz,
                                            MROWS, N_XZ, DMODEL, nullptr, 0);
    }
    // 2) depthwise conv + SiLU -> (xah, xal) split
    conv_silu_kernel<<<(MROWS * DINNER) / 256, 256>>>(conv_w, conv_b);

    // 3) dt = softplus(x_act @ W_dt^T + b_dt) -> g_dt
    {
        dim3 grid(DINNER / 128, MROWS / 128);
        gemm_mma<<<grid, GTHREADS, SMEMB>>>(xah, xal, wdh, wdl, dt,
                                            MROWS, DINNER, DINNER, b_dt, 1);
    }
    // 4) selective scan + gate -> (ygh, ygl) split
    scan_kernel<<<BSZ * (DINNER / 16), 256>>>(A_log, Dp);

    // 5) out = y_gated @ W_out^T   [4096,2048] x [1024,2048]^T -> [4096,1024]
    {
        dim3 grid(DMODEL / 128, MROWS / 128);
        gemm_mma<<<grid, GTHREADS, SMEMB>>>(ygh, ygl, woh, wol, out,
                                            MROWS, DMODEL, DINNER, nullptr, 0);
    }
}

// round 13
// speedup vs baseline: 4.8071x; 1.1989x over previous
#include <cuda_runtime.h>
#include <cuda_bf16.h>
#include <cuda_fp16.h>
#include <cstdint>

// Problem dims (fixed)
#define BSZ      2
#define LEN      2048
#define DMODEL   1024
#define DSTATE   16
#define DCONV    4
#define DINNER   2048
#define MROWS    (BSZ * LEN)          // 4096
#define N_XZ     (2 * DINNER)         // 4096

// ---------------- scratch (device globals; no allocs allowed) ----------------
__device__ float g_xz[(size_t)MROWS * N_XZ];       // [4096, 4096]  x_proj | z
__device__ float g_dt[(size_t)MROWS * DINNER];     // [4096, 2048]

// fp16 split buffers: activations as (hi, lo) pair (exact to 2^-22);
// weights as single rounded fp16 (error 2^-12, the only approximation).
__device__ __half g_xh[(size_t)MROWS * DMODEL],  g_xl[(size_t)MROWS * DMODEL];
__device__ __half g_wih[(size_t)N_XZ * DMODEL];
__device__ __half g_xah[(size_t)MROWS * DINNER], g_xal[(size_t)MROWS * DINNER];
__device__ __half g_wdh[(size_t)DINNER * DINNER];
__device__ __half g_ygh[(size_t)MROWS * DINNER], g_ygl[(size_t)MROWS * DINNER];
__device__ __half g_woh[(size_t)DMODEL * DINNER];

// ---------------- fast math helpers (FMA-pipe exp2, avoid MUFU storms) -------
__device__ __forceinline__ float fexp2(float x) {
    x = fminf(fmaxf(x, -125.0f), 125.0f);
    float r = rintf(x);
    float f = x - r;
    float p = 1.5403530e-4f;
    p = fmaf(p, f, 1.3333558e-3f);
    p = fmaf(p, f, 9.6181291e-3f);
    p = fmaf(p, f, 5.5504109e-2f);
    p = fmaf(p, f, 2.4022651e-1f);
    p = fmaf(p, f, 6.9314718e-1f);
    p = fmaf(p, f, 1.0f);
    int ir = (int)r;
    float sc = __int_as_float((ir + 127) << 23);
    return p * sc;
}
#define LOG2E 1.44269504f

__device__ __forceinline__ float fast_sigmoid(float x) {
    float e = fexp2(-x * LOG2E);
    return __fdividef(1.0f, 1.0f + e);
}
__device__ __forceinline__ float fast_softplus(float v) {
    float e = fexp2(-fabsf(v) * LOG2E);
    return fmaxf(v, 0.0f) + __logf(1.0f + e);
}

// ---------------- generic-PTX tensor helpers (sm_80+, compiles on compute_103)
__device__ __forceinline__ uint32_t smem_u32(const void* p) {
    uint32_t a;
    asm("{ .reg .u64 t; cvta.to.shared.u64 t, %1; cvt.u32.u64 %0, t; }" : "=r"(a) : "l"(p));
    return a;
}
__device__ __forceinline__ void cpasync16(uint32_t dst, const void* src) {
    asm volatile("cp.async.cg.shared.global [%0], [%1], 16;" :: "r"(dst), "l"(src));
}
__device__ __forceinline__ void cp_commit() {
    asm volatile("cp.async.commit_group;" ::: "memory");
}
__device__ __forceinline__ void ldsm4(uint32_t* r, uint32_t addr) {
    asm volatile("ldmatrix.sync.aligned.m8n8.x4.shared.b16 {%0,%1,%2,%3}, [%4];"
                 : "=r"(r[0]), "=r"(r[1]), "=r"(r[2]), "=r"(r[3]) : "r"(addr));
}
// non-volatile: pure register op, lets ptxas schedule/pipeline HMMA
__device__ __forceinline__ void mma16816(float* c, const uint32_t* a, const uint32_t* b) {
    asm("mma.sync.aligned.m16n8k16.row.col.f32.f16.f16.f32 "
        "{%0,%1,%2,%3}, {%4,%5,%6,%7}, {%8,%9}, {%0,%1,%2,%3};"
        : "+f"(c[0]), "+f"(c[1]), "+f"(c[2]), "+f"(c[3])
        : "r"(a[0]), "r"(a[1]), "r"(a[2]), "r"(a[3]), "r"(b[0]), "r"(b[1]));
}

// ---------------- fp16 2-pass HMMA GEMM --------------------------------------
// C[M,N] = A[M,K] @ B[N,K]^T with A = Ah+Al (exact fp16 pair), B = Bh (fp16).
// C = Ah*Bh + Al*Bh = A*Bh exactly; only error is B's fp16 rounding (~2^-12).
// CTA tile 128x128, K chunk 64, 16 warps (4m x 4n), warp tile 32x32.
// 3-stage cp.async ring, one barrier per chunk, pass-major MMA ordering.
// epi: 0 = plain store, 1 = softplus(acc + bias[n]).
#define RS     72                      // smem row stride in halves (padded, 144B)
#define TILEB  (128 * RS * 2)          // 18432 B per tile
#define BUFB   (3 * TILEB)             // Ah, Al, Bh
#define NSTAGE 3
#define SMEMB  (NSTAGE * BUFB)         // 165888 B
#define GTHREADS 512

__device__ __forceinline__ void load_tile_async(
    const __half* __restrict__ G, int ldk, int row0, int k0, uint32_t sm_tile)
{
    const int tid = threadIdx.x;
#pragma unroll
    for (int it = 0; it < 2; ++it) {
        int i = tid + it * GTHREADS;     // 1024 x 16B chunks
        int r = i >> 3;
        int s = i & 7;
        const void* src = G + (size_t)(row0 + r) * ldk + k0 + s * 8;
        uint32_t dst = sm_tile + (uint32_t)(r * RS + s * 8) * 2;
        cpasync16(dst, src);
    }
}

__device__ __forceinline__ void load_chunk(
    const __half* Ah, const __half* Al, const __half* Bh,
    int K, int arow, int brow, int k0, uint32_t stage_base)
{
    load_tile_async(Ah, K, arow, k0, stage_base + 0 * TILEB);
    load_tile_async(Al, K, arow, k0, stage_base + 1 * TILEB);
    load_tile_async(Bh, K, brow, k0, stage_base + 2 * TILEB);
}

__global__ void __launch_bounds__(GTHREADS, 1)
gemm_mma(const __half* __restrict__ Ah, const __half* __restrict__ Al,
         const __half* __restrict__ Bh,
         float* __restrict__ C, int M, int N, int K,
         const float* __restrict__ bias, int epi)
{
    extern __shared__ char smem[];
    const uint32_t sb = smem_u32(smem);
    const int tid = threadIdx.x;
    const int lane = tid & 31;
    const int wid = tid >> 5;
    const int warp_m = wid >> 2;       // 0..3
    const int warp_n = wid & 3;        // 0..3
    const int m0w = warp_m * 32;
    const int n0w = warp_n * 32;
    const int bx = blockIdx.x;         // N tile
    const int by = blockIdx.y;         // M tile
    const int arow = by * 128;
    const int brow = bx * 128;
    const int nchunk = K >> 6;

    // ldmatrix lane address offsets
    const int r_ = lane & 7, g = lane >> 3;
    const int aro = ((g & 1) << 3) + r_, ako = (g >> 1) << 3;   // A: m-row, k-col
    const int bro = ((g >> 1) << 3) + r_, bko = (g & 1) << 3;   // B: n-row, k-col

    float acc[2][4][4];
#pragma unroll
    for (int i = 0; i < 2; ++i)
#pragma unroll
        for (int j = 0; j < 4; ++j)
#pragma unroll
            for (int q = 0; q < 4; ++q) acc[i][j][q] = 0.0f;

    // prologue: chunks 0 and 1 into stages 0 and 1
    load_chunk(Ah, Al, Bh, K, arow, brow, 0, sb);
    cp_commit();
    if (1 < nchunk) load_chunk(Ah, Al, Bh, K, arow, brow, 64, sb + BUFB);
    cp_commit();

    int stage = 0;           // stage holding chunk c
    int lstage = 2 % NSTAGE; // stage to load chunk c+2 into

    for (int c = 0; c < nchunk; ++c) {
        asm volatile("cp.async.wait_group 1;" ::: "memory");
        __syncthreads();   // all warps: chunk c visible AND chunk c-1 compute done

        // issue loads for chunk c+2 into the stage freed by chunk c-1
        if (c + 2 < nchunk)
            load_chunk(Ah, Al, Bh, K, arow, brow, (c + 2) << 6, sb + lstage * BUFB);
        cp_commit();

        const uint32_t bufb = sb + stage * BUFB;
        const uint32_t Ah_t = bufb + 0 * TILEB;
        const uint32_t Al_t = bufb + 1 * TILEB;
        const uint32_t Bh_t = bufb + 2 * TILEB;

#pragma unroll
        for (int ks = 0; ks < 4; ++ks) {
            const int k0 = ks * 16;
            uint32_t ahf[2][4], alf[2][4];
#pragma unroll
            for (int mi = 0; mi < 2; ++mi) {
                uint32_t off = (uint32_t)((m0w + mi * 16 + aro) * RS + k0 + ako) * 2;
                ldsm4(ahf[mi], Ah_t + off);
                ldsm4(alf[mi], Al_t + off);
            }
            uint32_t bhf[2][4];
#pragma unroll
            for (int nq = 0; nq < 2; ++nq) {
                uint32_t off = (uint32_t)((n0w + nq * 16 + bro) * RS + k0 + bko) * 2;
                ldsm4(bhf[nq], Bh_t + off);
            }
            // pass-major ordering: 8 independent accumulators between reuses
#pragma unroll
            for (int mi = 0; mi < 2; ++mi)
#pragma unroll
                for (int nj = 0; nj < 4; ++nj)
                    mma16816(acc[mi][nj], ahf[mi], &bhf[nj >> 1][(nj & 1) * 2]);
#pragma unroll
            for (int mi = 0; mi < 2; ++mi)
#pragma unroll
                for (int nj = 0; nj < 4; ++nj)
                    mma16816(acc[mi][nj], alf[mi], &bhf[nj >> 1][(nj & 1) * 2]);
        }

        stage = (stage + 1 < NSTAGE) ? stage + 1 : 0;
        lstage = (lstage + 1 < NSTAGE) ? lstage + 1 : 0;
    }

    // epilogue: write C fragments
    const int rq = lane >> 2;          // 0..7
    const int cq = (lane & 3) * 2;     // 0,2,4,6
#pragma unroll
    for (int mi = 0; mi < 2; ++mi) {
        const int gm = arow + m0w + mi * 16;
#pragma unroll
        for (int nj = 0; nj < 4; ++nj) {
            const int gn = brow + n0w + nj * 8 + cq;
            float v0 = acc[mi][nj][0], v1 = acc[mi][nj][1];
            float v2 = acc[mi][nj][2], v3 = acc[mi][nj][3];
            if (epi == 1) {
                float b0 = __ldg(bias + gn), b1 = __ldg(bias + gn + 1);
                v0 = fast_softplus(v0 + b0);
                v1 = fast_softplus(v1 + b1);
                v2 = fast_softplus(v2 + b0);
                v3 = fast_softplus(v3 + b1);
            }
            *(float2*)(C + (size_t)(gm + rq) * N + gn)     = make_float2(v0, v1);
            *(float2*)(C + (size_t)(gm + 8 + rq) * N + gn) = make_float2(v2, v3);
        }
    }
}

// ---------------- fp32 -> (fp16 hi, fp16 lo) exact split ---------------------
__global__ void __launch_bounds__(256)
cvt_split(const float* __restrict__ s, __half* __restrict__ h,
          __half* __restrict__ l, int n)
{
    int i = (blockIdx.x * 256 + threadIdx.x) * 4;
    if (i < n) {
        float4 v = *(const float4*)(s + i);
        __half h0 = __float2half_rn(v.x), h1 = __float2half_rn(v.y);
        __half h2 = __float2half_rn(v.z), h3 = __float2half_rn(v.w);
        *(__half2*)(h + i)     = __halves2half2(h0, h1);
        *(__half2*)(h + i + 2) = __halves2half2(h2, h3);
        *(__half2*)(l + i)     = __halves2half2(
            __float2half_rn(v.x - __half2float(h0)),
            __float2half_rn(v.y - __half2float(h1)));
        *(__half2*)(l + i + 2) = __halves2half2(
            __float2half_rn(v.z - __half2float(h2)),
            __float2half_rn(v.w - __half2float(h3)));
    }
}

// ---------------- fp32 -> fp16 (weights, single) -----------------------------
__global__ void __launch_bounds__(256)
cvt_h(const float* __restrict__ s, __half* __restrict__ h, int n)
{
    int i = (blockIdx.x * 256 + threadIdx.x) * 4;
    if (i < n) {
        float4 v = *(const float4*)(s + i);
        *(__half2*)(h + i)     = __halves2half2(__float2half_rn(v.x), __float2half_rn(v.y));
        *(__half2*)(h + i + 2) = __halves2half2(__float2half_rn(v.z), __float2half_rn(v.w));
    }
}

// ---------------- depthwise causal conv1d (k=4) + SiLU -> split fp16 ---------
__global__ void __launch_bounds__(256)
conv_silu_kernel(const float* __restrict__ conv_w, const float* __restrict__ conv_b)
{
    int idx = blockIdx.x * blockDim.x + threadIdx.x;   // over MROWS*DINNER
    int d = idx & (DINNER - 1);
    int row = idx >> 11;            // b*L + t
    int t = row & (LEN - 1);

    float acc = conv_b[d];
    const float* w = conv_w + d * DCONV;
#pragma unroll
    for (int j = 0; j < DCONV; ++j) {
        int tt = t - (DCONV - 1) + j;
        if (tt >= 0)
            acc = fmaf(g_xz[(size_t)(row - (DCONV - 1) + j) * N_XZ + d], w[j], acc);
    }
    float v = acc * fast_sigmoid(acc);
    __half hi = __float2half_rn(v);
    g_xah[idx] = hi;
    g_xal[idx] = __float2half_rn(v - __half2float(hi));
}

// ---------------- selective scan + gating (smem-tiled) ------------------------
#define SCT 64                         // timesteps per tile
__global__ void __launch_bounds__(256)
scan_kernel(const float* __restrict__ A_log, const float* __restrict__ Dp)
{
    __shared__ float dt_s[SCT * 16];
    __shared__ float x_s[SCT * 16];
    __shared__ float z_s[SCT * 16];
    __shared__ float y_s[SCT * 16];

    const int tid = threadIdx.x;
    const int lane16 = tid & 15;           // state index s
    const int grp = tid >> 4;              // channel slot in block (0..15)
    const int b = blockIdx.x >> 7;         // 128 blocks per batch
    const int d0 = (blockIdx.x & 127) * 16;
    const int d = d0 + grp;

    const float a = -__expf(A_log[d * DSTATE + lane16]) * LOG2E;
    const float dp = Dp[d];

    const size_t rowbase = (size_t)(b * LEN);
    float h = 0.0f;

    for (int tile = 0; tile < LEN / SCT; ++tile) {
        const int t0 = tile * SCT;
#pragma unroll
        for (int it = 0; it < 4; ++it) {
            int e = tid + it * 256;
            int t = e >> 4, j = e & 15;
            size_t r = rowbase + t0 + t;
            size_t di = r * DINNER + d0 + j;
            dt_s[e] = g_dt[di];
            x_s[e]  = __half2float(g_xah[di]) + __half2float(g_xal[di]);
            z_s[e]  = g_xz[r * N_XZ + DINNER + d0 + j];
        }
        __syncthreads();

#pragma unroll 4
        for (int t = 0; t < SCT; ++t) {
            float dt = dt_s[t * 16 + grp];
            float xv = x_s[t * 16 + grp];
            float dA = fexp2(dt * a);
            h = fmaf(dA, h, dt * xv);

            float s = h;
            s += __shfl_xor_sync(0xffffffffu, s, 1);
            s += __shfl_xor_sync(0xffffffffu, s, 2);
            s += __shfl_xor_sync(0xffffffffu, s, 4);
            s += __shfl_xor_sync(0xffffffffu, s, 8);

            if (lane16 == 0) {
                float z = z_s[t * 16 + grp];
                y_s[t * 16 + grp] = (s + dp * xv) * (z * fast_sigmoid(z));
            }
        }
        __syncthreads();

#pragma unroll
        for (int it = 0; it < 4; ++it) {
            int e = tid + it * 256;
            int t = e >> 4, j = e & 15;
            float y = y_s[e];
            __half hi = __float2half_rn(y);
            size_t di = (rowbase + t0 + t) * DINNER + d0 + j;
            g_ygh[di] = hi;
            g_ygl[di] = __float2half_rn(y - __half2float(hi));
        }
        __syncthreads();
    }
}

// ---------------- launch ------------------------------------------------------
extern "C" void kernel_launch(void* const* d_in, const int* in_sizes, int n_in,
                              void* d_out, int out_size)
{
    const float* x      = (const float*)d_in[0];   // [2,2048,1024]
    const float* W_in   = (const float*)d_in[1];   // [4096,1024]
    const float* conv_w = (const float*)d_in[2];   // [2048,1,4]
    const float* conv_b = (const float*)d_in[3];   // [2048]
    const float* A_log  = (const float*)d_in[4];   // [2048,16]
    const float* Dp     = (const float*)d_in[5];   // [2048]
    const float* W_dt   = (const float*)d_in[6];   // [2048,2048]
    const float* b_dt   = (const float*)d_in[7];   // [2048]
    const float* W_out  = (const float*)d_in[8];   // [1024,2048]
    float* out = (float*)d_out;                    // [2,2048,1024]

    float* xz = nullptr;  cudaGetSymbolAddress((void**)&xz, g_xz);
    float* dt = nullptr;  cudaGetSymbolAddress((void**)&dt, g_dt);

    __half *xh, *xl, *wih, *xah, *xal, *wdh, *ygh, *ygl, *woh;
    cudaGetSymbolAddress((void**)&xh,  g_xh);  cudaGetSymbolAddress((void**)&xl,  g_xl);
    cudaGetSymbolAddress((void**)&wih, g_wih);
    cudaGetSymbolAddress((void**)&xah, g_xah); cudaGetSymbolAddress((void**)&xal, g_xal);
    cudaGetSymbolAddress((void**)&wdh, g_wdh);
    cudaGetSymbolAddress((void**)&ygh, g_ygh); cudaGetSymbolAddress((void**)&ygl, g_ygl);
    cudaGetSymbolAddress((void**)&woh, g_woh);

    cudaFuncSetAttribute(gemm_mma, cudaFuncAttributeMaxDynamicSharedMemorySize, SMEMB);

    // conversions for GEMM1
    cvt_split<<<(MROWS * DMODEL) / 1024, 256>>>(x, xh, xl, MROWS * DMODEL);
    cvt_h<<<(N_XZ * DMODEL) / 1024, 256>>>(W_in, wih, N_XZ * DMODEL);

    // 1) xz = x @ W_in^T   [4096,1024] x [4096,1024]^T -> [4096,4096]
    {
        dim3 grid(N_XZ / 128, MROWS / 128);
        gemm_mma<<<grid, GTHREADS, SMEMB>>>(xh, xl, wih, xz,
                                            MROWS, N_XZ, DMODEL, nullptr, 0);
    }
    // 2) depthwise conv + SiLU -> (xah, xal) split
    conv_silu_kernel<<<(MROWS * DINNER) / 256, 256>>>(conv_w, conv_b);
    cvt_h<<<(DINNER * DINNER) / 1024, 256>>>(W_dt, wdh, DINNER * DINNER);

    // 3) dt = softplus(x_act @ W_dt^T + b_dt) -> g_dt
    {
        dim3 grid(DINNER / 128, MROWS / 128);
        gemm_mma<<<grid, GTHREADS, SMEMB>>>(xah, xal, wdh, dt,
                                            MROWS, DINNER, DINNER, b_dt, 1);
    }
    // 4) selective scan + gate -> (ygh, ygl) split
    scan_kernel<<<BSZ * (DINNER / 16), 256>>>(A_log, Dp);
    cvt_h<<<(DMODEL * DINNER) / 1024, 256>>>(W_out, woh, DMODEL * DINNER);

    // 5) out = y_gated @ W_out^T   [4096,2048] x [1024,2048]^T -> [4096,1024]
    {
        dim3 grid(DMODEL / 128, MROWS / 128);
        gemm_mma<<<grid, GTHREADS, SMEMB>>>(ygh, ygl, woh, out,
                                            MROWS, DMODEL, DINNER, nullptr, 0);
    }
}

// round 15
// speedup vs baseline: 5.0960x; 1.0601x over previous
#include <cuda_runtime.h>
#include <cuda_bf16.h>
#include <cuda_fp16.h>
#include <cstdint>

// Problem dims (fixed)
#define BSZ      2
#define LEN      2048
#define DMODEL   1024
#define DSTATE   16
#define DCONV    4
#define DINNER   2048
#define MROWS    (BSZ * LEN)          // 4096
#define N_XZ     (2 * DINNER)         // 4096

// ---------------- scratch (device globals; no allocs allowed) ----------------
__device__ float g_xz[(size_t)MROWS * N_XZ];       // [4096, 4096]  x_proj | z
__device__ float g_dt[(size_t)MROWS * DINNER];     // [4096, 2048]

// fp16 split buffers: activations as (hi, lo) pair (exact to 2^-22);
// weights as single rounded fp16 (error 2^-12, the only approximation).
__device__ __half g_xh[(size_t)MROWS * DMODEL],  g_xl[(size_t)MROWS * DMODEL];
__device__ __half g_wih[(size_t)N_XZ * DMODEL];
__device__ __half g_xah[(size_t)MROWS * DINNER], g_xal[(size_t)MROWS * DINNER];
__device__ __half g_wdh[(size_t)DINNER * DINNER];
__device__ __half g_ygh[(size_t)MROWS * DINNER], g_ygl[(size_t)MROWS * DINNER];
__device__ __half g_woh[(size_t)DMODEL * DINNER];

// ---------------- fast math helpers (FMA-pipe exp2, avoid MUFU storms) -------
__device__ __forceinline__ float fexp2(float x) {
    x = fminf(fmaxf(x, -125.0f), 125.0f);
    float r = rintf(x);
    float f = x - r;
    float p = 1.5403530e-4f;
    p = fmaf(p, f, 1.3333558e-3f);
    p = fmaf(p, f, 9.6181291e-3f);
    p = fmaf(p, f, 5.5504109e-2f);
    p = fmaf(p, f, 2.4022651e-1f);
    p = fmaf(p, f, 6.9314718e-1f);
    p = fmaf(p, f, 1.0f);
    int ir = (int)r;
    float sc = __int_as_float((ir + 127) << 23);
    return p * sc;
}
#define LOG2E 1.44269504f

__device__ __forceinline__ float fast_sigmoid(float x) {
    float e = fexp2(-x * LOG2E);
    return __fdividef(1.0f, 1.0f + e);
}
__device__ __forceinline__ float fast_softplus(float v) {
    float e = fexp2(-fabsf(v) * LOG2E);
    return fmaxf(v, 0.0f) + __logf(1.0f + e);
}

// ---------------- generic-PTX tensor helpers (sm_80+, compiles on compute_103)
__device__ __forceinline__ uint32_t smem_u32(const void* p) {
    uint32_t a;
    asm("{ .reg .u64 t; cvta.to.shared.u64 t, %1; cvt.u32.u64 %0, t; }" : "=r"(a) : "l"(p));
    return a;
}
__device__ __forceinline__ void cpasync16(uint32_t dst, const void* src) {
    asm volatile("cp.async.cg.shared.global [%0], [%1], 16;" :: "r"(dst), "l"(src));
}
__device__ __forceinline__ void cp_commit() {
    asm volatile("cp.async.commit_group;" ::: "memory");
}
__device__ __forceinline__ void ldsm4(uint32_t* r, uint32_t addr) {
    asm volatile("ldmatrix.sync.aligned.m8n8.x4.shared.b16 {%0,%1,%2,%3}, [%4];"
                 : "=r"(r[0]), "=r"(r[1]), "=r"(r[2]), "=r"(r[3]) : "r"(addr));
}
// non-volatile: pure register op, lets ptxas schedule/pipeline HMMA
__device__ __forceinline__ void mma16816(float* c, const uint32_t* a, const uint32_t* b) {
    asm("mma.sync.aligned.m16n8k16.row.col.f32.f16.f16.f32 "
        "{%0,%1,%2,%3}, {%4,%5,%6,%7}, {%8,%9}, {%0,%1,%2,%3};"
        : "+f"(c[0]), "+f"(c[1]), "+f"(c[2]), "+f"(c[3])
        : "r"(a[0]), "r"(a[1]), "r"(a[2]), "r"(a[3]), "r"(b[0]), "r"(b[1]));
}

// ---------------- fp16 2-pass HMMA GEMM --------------------------------------
// C[M,N] = A[M,K] @ B[N,K]^T with A = Ah+Al (exact fp16 pair), B = Bh (fp16).
// C = Ah*Bh + Al*Bh = A*Bh exactly; only error is B's fp16 rounding (~2^-12).
// CTA tile 128(M) x 256(N), K chunk 64, 16 warps (4m x 4n), warp tile 32x64.
// 2-stage ring, depth-1 cp.async prefetch, ONE barrier per K-chunk.
// epi: 0 = plain store, 1 = softplus(acc + bias[n]).
#define RS     72                      // smem row stride in halves (padded, 144B)
#define ATILE  (128 * RS * 2)          // 18432 B
#define BTILE  (256 * RS * 2)          // 36864 B
#define STAGEB (2 * ATILE + BTILE)     // 73728 B : Ah, Al, Bh
#define SMEMB  (2 * STAGEB)            // 147456 B
#define GTHREADS 512

// rows128: iters=2 (A tiles), rows256: iters=4 (B tile)
__device__ __forceinline__ void load_rows(
    const __half* __restrict__ G, int ldk, int row0, int k0,
    uint32_t sm_tile, int iters)
{
    const int tid = threadIdx.x;
    for (int it = 0; it < iters; ++it) {
        int i = tid + it * GTHREADS;     // 16B chunks
        int r = i >> 3;
        int s = i & 7;
        const void* src = G + (size_t)(row0 + r) * ldk + k0 + s * 8;
        uint32_t dst = sm_tile + (uint32_t)(r * RS + s * 8) * 2;
        cpasync16(dst, src);
    }
}

__device__ __forceinline__ void load_stage(
    const __half* Ah, const __half* Al, const __half* Bh,
    int K, int arow, int brow, int k0, uint32_t stage_base)
{
    load_rows(Ah, K, arow, k0, stage_base, 2);
    load_rows(Al, K, arow, k0, stage_base + ATILE, 2);
    load_rows(Bh, K, brow, k0, stage_base + 2 * ATILE, 4);
}

__global__ void __launch_bounds__(GTHREADS, 1)
gemm_mma(const __half* __restrict__ Ah, const __half* __restrict__ Al,
         const __half* __restrict__ Bh,
         float* __restrict__ C, int M, int N, int K,
         const float* __restrict__ bias, int epi)
{
    extern __shared__ char smem[];
    const uint32_t sb = smem_u32(smem);
    const int tid = threadIdx.x;
    const int lane = tid & 31;
    const int wid = tid >> 5;
    const int warp_m = wid >> 2;       // 0..3
    const int warp_n = wid & 3;        // 0..3
    const int m0w = warp_m * 32;
    const int n0w = warp_n * 64;
    const int bx = blockIdx.x;         // N tile (256)
    const int by = blockIdx.y;         // M tile (128)
    const int arow = by * 128;
    const int brow = bx * 256;
    const int nchunk = K >> 6;

    // ldmatrix lane address offsets
    const int r_ = lane & 7, g = lane >> 3;
    const int aro = ((g & 1) << 3) + r_, ako = (g >> 1) << 3;   // A: m-row, k-col
    const int bro = ((g >> 1) << 3) + r_, bko = (g & 1) << 3;   // B: n-row, k-col

    float acc[2][8][4];
#pragma unroll
    for (int i = 0; i < 2; ++i)
#pragma unroll
        for (int j = 0; j < 8; ++j)
#pragma unroll
            for (int q = 0; q < 4; ++q) acc[i][j][q] = 0.0f;

    // prologue: chunk 0 into stage 0
    load_stage(Ah, Al, Bh, K, arow, brow, 0, sb);
    cp_commit();

    int stage = 0;
    for (int c = 0; c < nchunk; ++c) {
        asm volatile("cp.async.wait_group 0;" ::: "memory");
        __syncthreads();   // chunk c resident; all warps done with chunk c-1

        // depth-1 prefetch into the stage freed by chunk c-1
        if (c + 1 < nchunk) {
            load_stage(Ah, Al, Bh, K, arow, brow, (c + 1) << 6, sb + (stage ^ 1) * STAGEB);
            cp_commit();
        }

        const uint32_t bufb = sb + stage * STAGEB;
        const uint32_t Ah_t = bufb;
        const uint32_t Al_t = bufb + ATILE;
        const uint32_t Bh_t = bufb + 2 * ATILE;

#pragma unroll
        for (int ks = 0; ks < 4; ++ks) {
            const int k0 = ks * 16;
            uint32_t ahf[2][4], alf[2][4];
#pragma unroll
            for (int mi = 0; mi < 2; ++mi) {
                uint32_t off = (uint32_t)((m0w + mi * 16 + aro) * RS + k0 + ako) * 2;
                ldsm4(ahf[mi], Ah_t + off);
                ldsm4(alf[mi], Al_t + off);
            }
            uint32_t bhf[4][4];
#pragma unroll
            for (int nq = 0; nq < 4; ++nq) {
                uint32_t off = (uint32_t)((n0w + nq * 16 + bro) * RS + k0 + bko) * 2;
                ldsm4(bhf[nq], Bh_t + off);
            }
            // pass-major ordering: 16 independent accumulators between reuses
#pragma unroll
            for (int mi = 0; mi < 2; ++mi)
#pragma unroll
                for (int nj = 0; nj < 8; ++nj)
                    mma16816(acc[mi][nj], ahf[mi], &bhf[nj >> 1][(nj & 1) * 2]);
#pragma unroll
            for (int mi = 0; mi < 2; ++mi)
#pragma unroll
                for (int nj = 0; nj < 8; ++nj)
                    mma16816(acc[mi][nj], alf[mi], &bhf[nj >> 1][(nj & 1) * 2]);
        }
        stage ^= 1;
    }

    // epilogue: write C fragments
    const int rq = lane >> 2;          // 0..7
    const int cq = (lane & 3) * 2;     // 0,2,4,6
#pragma unroll
    for (int mi = 0; mi < 2; ++mi) {
        const int gm = arow + m0w + mi * 16;
#pragma unroll
        for (int nj = 0; nj < 8; ++nj) {
            const int gn = brow + n0w + nj * 8 + cq;
            float v0 = acc[mi][nj][0], v1 = acc[mi][nj][1];
            float v2 = acc[mi][nj][2], v3 = acc[mi][nj][3];
            if (epi == 1) {
                float b0 = __ldg(bias + gn), b1 = __ldg(bias + gn + 1);
                v0 = fast_softplus(v0 + b0);
                v1 = fast_softplus(v1 + b1);
                v2 = fast_softplus(v2 + b0);
                v3 = fast_softplus(v3 + b1);
            }
            *(float2*)(C + (size_t)(gm + rq) * N + gn)     = make_float2(v0, v1);
            *(float2*)(C + (size_t)(gm + 8 + rq) * N + gn) = make_float2(v2, v3);
        }
    }
}

// ---------------- fp32 -> (fp16 hi, fp16 lo) exact split ---------------------
__global__ void __launch_bounds__(256)
cvt_split(const float* __restrict__ s, __half* __restrict__ h,
          __half* __restrict__ l, int n)
{
    int i = (blockIdx.x * 256 + threadIdx.x) * 4;
    if (i < n) {
        float4 v = *(const float4*)(s + i);
        __half h0 = __float2half_rn(v.x), h1 = __float2half_rn(v.y);
        __half h2 = __float2half_rn(v.z), h3 = __float2half_rn(v.w);
        *(__half2*)(h + i)     = __halves2half2(h0, h1);
        *(__half2*)(h + i + 2) = __halves2half2(h2, h3);
        *(__half2*)(l + i)     = __halves2half2(
            __float2half_rn(v.x - __half2float(h0)),
            __float2half_rn(v.y - __half2float(h1)));
        *(__half2*)(l + i + 2) = __halves2half2(
            __float2half_rn(v.z - __half2float(h2)),
            __float2half_rn(v.w - __half2float(h3)));
    }
}

// ---------------- fp32 -> fp16 (weights, single) -----------------------------
__global__ void __launch_bounds__(256)
cvt_h(const float* __restrict__ s, __half* __restrict__ h, int n)
{
    int i = (blockIdx.x * 256 + threadIdx.x) * 4;
    if (i < n) {
        float4 v = *(const float4*)(s + i);
        *(__half2*)(h + i)     = __halves2half2(__float2half_rn(v.x), __float2half_rn(v.y));
        *(__half2*)(h + i + 2) = __halves2half2(__float2half_rn(v.z), __float2half_rn(v.w));
    }
}

// ---------------- depthwise causal conv1d (k=4) + SiLU -> split fp16 ---------
__global__ void __launch_bounds__(256)
conv_silu_kernel(const float* __restrict__ conv_w, const float* __restrict__ conv_b)
{
    int idx = blockIdx.x * blockDim.x + threadIdx.x;   // over MROWS*DINNER
    int d = idx & (DINNER - 1);
    int row = idx >> 11;            // b*L + t
    int t = row & (LEN - 1);

    float acc = conv_b[d];
    const float* w = conv_w + d * DCONV;
#pragma unroll
    for (int j = 0; j < DCONV; ++j) {
        int tt = t - (DCONV - 1) + j;
        if (tt >= 0)
            acc = fmaf(g_xz[(size_t)(row - (DCONV - 1) + j) * N_XZ + d], w[j], acc);
    }
    float v = acc * fast_sigmoid(acc);
    __half hi = __float2half_rn(v);
    g_xah[idx] = hi;
    g_xal[idx] = __float2half_rn(v - __half2float(hi));
}

// ---------------- selective scan + gating (smem-tiled) ------------------------
#define SCT 64                         // timesteps per tile
__global__ void __launch_bounds__(256)
scan_kernel(const float* __restrict__ A_log, const float* __restrict__ Dp)
{
    __shared__ float dt_s[SCT * 16];
    __shared__ float x_s[SCT * 16];
    __shared__ float z_s[SCT * 16];
    __shared__ float y_s[SCT * 16];

    const int tid = threadIdx.x;
    const int lane16 = tid & 15;           // state index s
    const int grp = tid >> 4;              // channel slot in block (0..15)
    const int b = blockIdx.x >> 7;         // 128 blocks per batch
    const int d0 = (blockIdx.x & 127) * 16;
    const int d = d0 + grp;

    const float a = -__expf(A_log[d * DSTATE + lane16]) * LOG2E;
    const float dp = Dp[d];

    const size_t rowbase = (size_t)(b * LEN);
    float h = 0.0f;

    for (int tile = 0; tile < LEN / SCT; ++tile) {
        const int t0 = tile * SCT;
#pragma unroll
        for (int it = 0; it < 4; ++it) {
            int e = tid + it * 256;
            int t = e >> 4, j = e & 15;
            size_t r = rowbase + t0 + t;
            size_t di = r * DINNER + d0 + j;
            dt_s[e] = g_dt[di];
            x_s[e]  = __half2float(g_xah[di]) + __half2float(g_xal[di]);
            z_s[e]  = g_xz[r * N_XZ + DINNER + d0 + j];
        }
        __syncthreads();

#pragma unroll 4
        for (int t = 0; t < SCT; ++t) {
            float dt = dt_s[t * 16 + grp];
            float xv = x_s[t * 16 + grp];
            float dA = fexp2(dt * a);
            h = fmaf(dA, h, dt * xv);

            float s = h;
            s += __shfl_xor_sync(0xffffffffu, s, 1);
            s += __shfl_xor_sync(0xffffffffu, s, 2);
            s += __shfl_xor_sync(0xffffffffu, s, 4);
            s += __shfl_xor_sync(0xffffffffu, s, 8);

            if (lane16 == 0) {
                float z = z_s[t * 16 + grp];
                y_s[t * 16 + grp] = (s + dp * xv) * (z * fast_sigmoid(z));
            }
        }
        __syncthreads();

#pragma unroll
        for (int it = 0; it < 4; ++it) {
            int e = tid + it * 256;
            int t = e >> 4, j = e & 15;
            float y = y_s[e];
            __half hi = __float2half_rn(y);
            size_t di = (rowbase + t0 + t) * DINNER + d0 + j;
            g_ygh[di] = hi;
            g_ygl[di] = __float2half_rn(y - __half2float(hi));
        }
        __syncthreads();
    }
}

// ---------------- launch ------------------------------------------------------
extern "C" void kernel_launch(void* const* d_in, const int* in_sizes, int n_in,
                              void* d_out, int out_size)
{
    const float* x      = (const float*)d_in[0];   // [2,2048,1024]
    const float* W_in   = (const float*)d_in[1];   // [4096,1024]
    const float* conv_w = (const float*)d_in[2];   // [2048,1,4]
    const float* conv_b = (const float*)d_in[3];   // [2048]
    const float* A_log  = (const float*)d_in[4];   // [2048,16]
    const float* Dp     = (const float*)d_in[5];   // [2048]
    const float* W_dt   = (const float*)d_in[6];   // [2048,2048]
    const float* b_dt   = (const float*)d_in[7];   // [2048]
    const float* W_out  = (const float*)d_in[8];   // [1024,2048]
    float* out = (float*)d_out;                    // [2,2048,1024]

    float* xz = nullptr;  cudaGetSymbolAddress((void**)&xz, g_xz);
    float* dt = nullptr;  cudaGetSymbolAddress((void**)&dt, g_dt);

    __half *xh, *xl, *wih, *xah, *xal, *wdh, *ygh, *ygl, *woh;
    cudaGetSymbolAddress((void**)&xh,  g_xh);  cudaGetSymbolAddress((void**)&xl,  g_xl);
    cudaGetSymbolAddress((void**)&wih, g_wih);
    cudaGetSymbolAddress((void**)&xah, g_xah); cudaGetSymbolAddress((void**)&xal, g_xal);
    cudaGetSymbolAddress((void**)&wdh, g_wdh);
    cudaGetSymbolAddress((void**)&ygh, g_ygh); cudaGetSymbolAddress((void**)&ygl, g_ygl);
    cudaGetSymbolAddress((void**)&woh, g_woh);

    cudaFuncSetAttribute(gemm_mma, cudaFuncAttributeMaxDynamicSharedMemorySize, SMEMB);

    // conversions for GEMM1
    cvt_split<<<(MROWS * DMODEL) / 1024, 256>>>(x, xh, xl, MROWS * DMODEL);
    cvt_h<<<(N_XZ * DMODEL) / 1024, 256>>>(W_in, wih, N_XZ * DMODEL);

    // 1) xz = x @ W_in^T   [4096,1024] x [4096,1024]^T -> [4096,4096]
    {
        dim3 grid(N_XZ / 256, MROWS / 128);
        gemm_mma<<<grid, GTHREADS, SMEMB>>>(xh, xl, wih, xz,
                                            MROWS, N_XZ, DMODEL, nullptr, 0);
    }
    // 2) depthwise conv + SiLU -> (xah, xal) split
    conv_silu_kernel<<<(MROWS * DINNER) / 256, 256>>>(conv_w, conv_b);
    cvt_h<<<(DINNER * DINNER) / 1024, 256>>>(W_dt, wdh, DINNER * DINNER);

    // 3) dt = softplus(x_act @ W_dt^T + b_dt) -> g_dt
    {
        dim3 grid(DINNER / 256, MROWS / 128);
        gemm_mma<<<grid, GTHREADS, SMEMB>>>(xah, xal, wdh, dt,
                                            MROWS, DINNER, DINNER, b_dt, 1);
    }
    // 4) selective scan + gate -> (ygh, ygl) split
    scan_kernel<<<BSZ * (DINNER / 16), 256>>>(A_log, Dp);
    cvt_h<<<(DMODEL * DINNER) / 1024, 256>>>(W_out, woh, DMODEL * DINNER);

    // 5) out = y_gated @ W_out^T   [4096,2048] x [1024,2048]^T -> [4096,1024]
    {
        dim3 grid(DMODEL / 256, MROWS / 128);
        gemm_mma<<<grid, GTHREADS, SMEMB>>>(ygh, ygl, woh, out,
                                            MROWS, DMODEL, DINNER, nullptr, 0);
    }
}